// round 4
// baseline (speedup 1.0000x reference)
#include <cuda_runtime.h>
#include <math.h>
#include <stdint.h>

#define NN 50000
#define EE 800000
#define BB 256
#define DD 128
#define TT 8
#define KV_OFF (BB*TT*DD)

// ---------------- scratch (no allocations allowed) ----------------
__device__ float g_h[(size_t)NN*DD];        // post-attention node states
__device__ float g_KV[2*BB*TT*DD];          // Kc then Vc
__device__ float g_lip[BB*9];               // lattice inner products
__device__ float g_agg[(size_t)NN*DD];      // scatter sums
__device__ int   g_cnt[NN];                 // scatter counts

__device__ __forceinline__ float silu_f(float x) {
    return __fdividef(x, 1.f + __expf(-x));
}

__device__ __forceinline__ void mma_tf32(float* c, const uint32_t* a, const uint32_t* b) {
    asm volatile(
        "mma.sync.aligned.m16n8k8.row.col.f32.tf32.tf32.f32 "
        "{%0,%1,%2,%3}, {%4,%5,%6,%7}, {%8,%9}, {%0,%1,%2,%3};\n"
        : "+f"(c[0]), "+f"(c[1]), "+f"(c[2]), "+f"(c[3])
        : "r"(a[0]), "r"(a[1]), "r"(a[2]), "r"(a[3]), "r"(b[0]), "r"(b[1]));
}

__device__ __forceinline__ void cpa16(float* dst, const float* src) {
    uint32_t d = (uint32_t)__cvta_generic_to_shared(dst);
    asm volatile("cp.async.cg.shared.global [%0], [%1], 16;" :: "r"(d), "l"(src));
}
#define CP_COMMIT asm volatile("cp.async.commit_group;" ::: "memory")
#define CP_WAIT0  asm volatile("cp.async.wait_group 0;" ::: "memory")

// ---------------- kernel 1: K/V projection + lattice gram ----------------
__global__ void prep_kernel(const float* __restrict__ cond,
                            const float* __restrict__ wk, const float* __restrict__ bk,
                            const float* __restrict__ wv, const float* __restrict__ bv,
                            const float* __restrict__ lat)
{
    int b = blockIdx.x;
    if (b < BB*TT) {
        __shared__ float s_c[DD];
        int d = threadIdx.x;
        s_c[d] = cond[b*DD + d];
        __syncthreads();
        float ka = bk[d], va = bv[d];
        #pragma unroll 8
        for (int k = 0; k < DD; k++) {
            float c = s_c[k];
            ka = fmaf(c, wk[k*DD + d], ka);
            va = fmaf(c, wv[k*DD + d], va);
        }
        g_KV[b*DD + d] = ka;
        g_KV[KV_OFF + b*DD + d] = va;
    } else {
        int bb = b - BB*TT;
        int t = threadIdx.x;
        if (t < 9) {
            int i = t / 3, k2 = t % 3;
            const float* L = lat + bb*9;
            g_lip[bb*9 + t] = L[i*3+0]*L[k2*3+0] + L[i*3+1]*L[k2*3+1] + L[i*3+2]*L[k2*3+2];
        }
    }
}

// ---------------- kernel 2: zero scatter buffers ----------------
__global__ void zero_kernel()
{
    int idx = blockIdx.x * blockDim.x + threadIdx.x;
    if (idx < NN*DD) g_agg[idx] = 0.f;
    if (idx < NN)    g_cnt[idx] = 0;
}

// ---------------- kernel 3: cross-attention with spatial bias ----------------
__global__ __launch_bounds__(512, 1)
void attn_kernel(const float* __restrict__ nfeat, const float* __restrict__ frac,
                 const int* __restrict__ n2g,
                 const float* __restrict__ wq, const float* __restrict__ bq,
                 const float* __restrict__ wo, const float* __restrict__ bo,
                 const float* __restrict__ sw1, const float* __restrict__ sb1,
                 const float* __restrict__ sw2, const float* __restrict__ sb2)
{
    extern __shared__ float sm[];
    float* s_wq  = sm;                 // 16384
    float* s_wo  = s_wq + 16384;       // 16384
    float* s_sw1 = s_wo + 16384;       // 3072
    float* s_sw2 = s_sw1 + 3072;       // 1024
    float* s_bq  = s_sw2 + 1024;       // 128
    float* s_bo  = s_bq + 128;         // 128
    float* s_sb1 = s_bo + 128;         // 128
    float* s_sb2 = s_sb1 + 128;        // 8
    float* s_h   = s_sb2 + 8;          // 512
    float* s_q   = s_h + 512;          // 512
    float* s_hid = s_q + 512;          // 512
    float* s_ca  = s_hid + 512;        // 512
    float* s_enc = s_ca + 512;         // 96
    float* s_att = s_enc + 96;         // 32

    int tid = threadIdx.x;
    for (int i = tid; i < 16384; i += 512) { s_wq[i] = wq[i]; s_wo[i] = wo[i]; }
    for (int i = tid; i < 3072; i += 512) s_sw1[i] = sw1[i];
    for (int i = tid; i < 1024; i += 512) s_sw2[i] = sw2[i];
    if (tid < 128) { s_bq[tid] = bq[tid]; s_bo[tid] = bo[tid]; s_sb1[tid] = sb1[tid]; }
    if (tid < 8) s_sb2[tid] = sb2[tid];
    __syncthreads();

    int sub = tid >> 7, d = tid & 127;
    int ngroups = (NN + 3) >> 2;
    for (int grp = blockIdx.x; grp < ngroups; grp += gridDim.x) {
        int n = grp*4 + sub;
        bool act = n < NN;
        int g = act ? n2g[n] : 0;
        float hv = act ? nfeat[(size_t)n*DD + d] : 0.f;
        s_h[sub*DD + d] = hv;
        if (d < 24 && act) {
            int ii = d % 12, c = ii >> 2, j = ii & 3;
            float ph = frac[n*3 + c] * ((float)(1 << j) * 3.14159265358979323846f);
            s_enc[sub*24 + d] = (d < 12) ? sinf(ph) : cosf(ph);
        }
        __syncthreads();

        {
            float acc = s_bq[d];
            const float* hh = s_h + sub*DD;
            #pragma unroll 8
            for (int k = 0; k < DD; k++) acc = fmaf(hh[k], s_wq[k*DD + d], acc);
            s_q[sub*DD + d] = acc;
            float ha = s_sb1[d];
            const float* ee = s_enc + sub*24;
            #pragma unroll
            for (int k = 0; k < 24; k++) ha = fmaf(ee[k], s_sw1[k*DD + d], ha);
            s_hid[sub*DD + d] = silu_f(ha);
        }
        __syncthreads();

        {
            int t = d >> 4, lane = d & 15;
            float sc = 0.f, bi = 0.f;
            const float* Kr = g_KV + ((size_t)(g*TT + t))*DD;
            const float* qq = s_q + sub*DD;
            const float* hh2 = s_hid + sub*DD;
            #pragma unroll
            for (int k = lane; k < DD; k += 16) {
                sc = fmaf(qq[k], Kr[k], sc);
                bi = fmaf(hh2[k], s_sw2[k*8 + t], bi);
            }
            #pragma unroll
            for (int o = 8; o > 0; o >>= 1) {
                sc += __shfl_down_sync(0xffffffffu, sc, o, 16);
                bi += __shfl_down_sync(0xffffffffu, bi, o, 16);
            }
            if (lane == 0)
                s_att[sub*8 + t] = sc * 0.08838834764831845f + bi + s_sb2[t];
        }
        __syncthreads();
        if (d == 0) {
            float* a = s_att + sub*8;
            float m = a[0];
            #pragma unroll
            for (int u = 1; u < 8; u++) m = fmaxf(m, a[u]);
            float s = 0.f, ex[8];
            #pragma unroll
            for (int u = 0; u < 8; u++) { ex[u] = __expf(a[u] - m); s += ex[u]; }
            float inv = __fdividef(1.f, s);
            #pragma unroll
            for (int u = 0; u < 8; u++) a[u] = ex[u] * inv;
        }
        __syncthreads();
        {
            const float* Vr = g_KV + KV_OFF + ((size_t)(g*TT))*DD;
            float ca = 0.f;
            #pragma unroll
            for (int u = 0; u < 8; u++) ca = fmaf(s_att[sub*8 + u], Vr[u*DD + d], ca);
            s_ca[sub*DD + d] = ca;
        }
        __syncthreads();
        {
            float out = hv + s_bo[d];
            const float* cc = s_ca + sub*DD;
            #pragma unroll 8
            for (int k = 0; k < DD; k++) out = fmaf(cc[k], s_wo[k*DD + d], out);
            if (act) g_h[(size_t)n*DD + d] = out;
        }
        __syncthreads();
    }
}

// ---------------- kernel 4: edge MLP, 16 warps, cp.async pipelined ----------------
// Block tile: 128 edges x 128 outs. 16 warps 4x4, warp tile 32x32 (2 mfrag x 4 nfrag).
#define TM 128
#define SA 276     // A row stride; 276%32=20 -> conflict-free frags
#define SB 136     // B row stride; 136%32=8  -> conflict-free frags
#define BBF (16*SB)

__global__ __launch_bounds__(512, 1)
void edge_kernel(const float* __restrict__ frac,
                 const int* __restrict__ edges, const int* __restrict__ e2g,
                 const float* __restrict__ ew1, const float* __restrict__ eb1,
                 const float* __restrict__ ew2, const float* __restrict__ eb2)
{
    extern __shared__ float sm[];
    float* s_a  = sm;             // TM*SA
    float* s_bb = sm + TM*SA;     // 2*BBF double buffer
    __shared__ int s_i[TM], s_j[TM];

    int tid  = threadIdx.x;
    int lane = tid & 31;
    int wid  = tid >> 5;
    int wm = wid >> 2;            // 0..3
    int wn = wid & 3;             // 0..3
    int e0 = blockIdx.x * TM;
    int brow = tid >> 5, bc4 = (tid & 31) * 4;   // B chunk coop-load coords

    if (tid < TM) {
        s_i[tid] = edges[e0 + tid];
        s_j[tid] = edges[EE + e0 + tid];
    }
    __syncthreads();

    // async gather A (raw fp32; HMMA truncates to tf32)
    #pragma unroll
    for (int it = 0; it < 16; it++) {
        int idx = tid + it*512;
        int r = idx >> 5, c4 = (idx & 31) * 4;
        int e = r >> 1, p = r & 1;
        int node = p ? s_j[e] : s_i[e];
        cpa16(s_a + e*SA + p*DD + c4, g_h + (size_t)node*DD + c4);
    }
    // ew1 chunk 0 -> buf0
    cpa16(s_bb + brow*SB + bc4, ew1 + (size_t)brow*DD + bc4);
    CP_COMMIT;

    // scalar tail columns + counts (overlap with cp.async flight)
    if (tid < TM) {
        int e = tid;
        const float* lp = g_lip + e2g[e0 + e]*9;
        #pragma unroll
        for (int u = 0; u < 9; u++) s_a[e*SA + 256 + u] = lp[u];
        int ii = s_i[e], jj = s_j[e];
        #pragma unroll
        for (int c = 0; c < 3; c++) {
            float dd = frac[jj*3 + c] - frac[ii*3 + c];
            dd -= floorf(dd);
            s_a[e*SA + 265 + c] = dd;
        }
        #pragma unroll
        for (int u = 268; u < 276; u++) s_a[e*SA + u] = 0.f;
        atomicAdd(&g_cnt[ii], 1);
    }

    float acc[2][4][4];
    #pragma unroll
    for (int mf = 0; mf < 2; mf++)
        #pragma unroll
        for (int nf = 0; nf < 4; nf++)
            #pragma unroll
            for (int u = 0; u < 4; u++) acc[mf][nf][u] = 0.f;

    CP_WAIT0;
    __syncthreads();

    // ---- GEMM1: 17 chunks of 16 k-rows (k=272; invalid rows clamp to 267, A cols zero) ----
    for (int ct = 0; ct < 17; ct++) {
        if (ct < 16) {
            int kr = min(ct*16 + 16 + brow, 267);
            cpa16(s_bb + ((ct+1)&1)*BBF + brow*SB + bc4, ew1 + (size_t)kr*DD + bc4);
        } else {
            // prefetch ew2 chunk 0 -> buf1 ((17)&1 == 1)
            cpa16(s_bb + BBF + brow*SB + bc4, ew2 + (size_t)brow*DD + bc4);
        }
        CP_COMMIT;

        const float* bB = s_bb + (ct & 1)*BBF;
        #pragma unroll
        for (int kk = 0; kk < 16; kk += 8) {
            int kg = ct*16 + kk;
            uint32_t afr[2][4];
            #pragma unroll
            for (int mf = 0; mf < 2; mf++) {
                const float* ap = s_a + (wm*32 + mf*16 + (lane >> 2))*SA + kg + (lane & 3);
                afr[mf][0] = __float_as_uint(ap[0]);
                afr[mf][1] = __float_as_uint(ap[8*SA]);
                afr[mf][2] = __float_as_uint(ap[4]);
                afr[mf][3] = __float_as_uint(ap[8*SA + 4]);
            }
            uint32_t bfr[4][2];
            #pragma unroll
            for (int nf = 0; nf < 4; nf++) {
                const float* bp = bB + (kk + (lane & 3))*SB + wn*32 + nf*8 + (lane >> 2);
                bfr[nf][0] = __float_as_uint(bp[0]);
                bfr[nf][1] = __float_as_uint(bp[4*SB]);
            }
            #pragma unroll
            for (int mf = 0; mf < 2; mf++)
                #pragma unroll
                for (int nf = 0; nf < 4; nf++)
                    mma_tf32(acc[mf][nf], afr[mf], bfr[nf]);
        }
        CP_WAIT0;
        __syncthreads();
    }

    // ---- hidden = silu(acc + eb1) -> s_a cols 0..127 ----
    #pragma unroll
    for (int mf = 0; mf < 2; mf++) {
        int r0 = wm*32 + mf*16 + (lane >> 2);
        #pragma unroll
        for (int nf = 0; nf < 4; nf++) {
            int n = wn*32 + nf*8 + (lane & 3)*2;
            float b0 = eb1[n], b1 = eb1[n + 1];
            s_a[r0*SA + n]           = silu_f(acc[mf][nf][0] + b0);
            s_a[r0*SA + n + 1]       = silu_f(acc[mf][nf][1] + b1);
            s_a[(r0 + 8)*SA + n]     = silu_f(acc[mf][nf][2] + b0);
            s_a[(r0 + 8)*SA + n + 1] = silu_f(acc[mf][nf][3] + b1);
            #pragma unroll
            for (int u = 0; u < 4; u++) acc[mf][nf][u] = 0.f;
        }
    }
    __syncthreads();

    // ---- GEMM2: 8 chunks of ew2; chunk c lives in buf[(1+c)&1] ----
    for (int c = 0; c < 8; c++) {
        if (c < 7) {
            cpa16(s_bb + (c & 1)*BBF + brow*SB + bc4,
                  ew2 + (size_t)(c*16 + 16 + brow)*DD + bc4);
            CP_COMMIT;
        }
        const float* bB = s_bb + ((1 + c) & 1)*BBF;
        #pragma unroll
        for (int kk = 0; kk < 16; kk += 8) {
            int kg = c*16 + kk;
            uint32_t afr[2][4];
            #pragma unroll
            for (int mf = 0; mf < 2; mf++) {
                const float* ap = s_a + (wm*32 + mf*16 + (lane >> 2))*SA + kg + (lane & 3);
                afr[mf][0] = __float_as_uint(ap[0]);
                afr[mf][1] = __float_as_uint(ap[8*SA]);
                afr[mf][2] = __float_as_uint(ap[4]);
                afr[mf][3] = __float_as_uint(ap[8*SA + 4]);
            }
            uint32_t bfr[4][2];
            #pragma unroll
            for (int nf = 0; nf < 4; nf++) {
                const float* bp = bB + (kk + (lane & 3))*SB + wn*32 + nf*8 + (lane >> 2);
                bfr[nf][0] = __float_as_uint(bp[0]);
                bfr[nf][1] = __float_as_uint(bp[4*SB]);
            }
            #pragma unroll
            for (int mf = 0; mf < 2; mf++)
                #pragma unroll
                for (int nf = 0; nf < 4; nf++)
                    mma_tf32(acc[mf][nf], afr[mf], bfr[nf]);
        }
        if (c < 7) { CP_WAIT0; }
        __syncthreads();
    }

    // ---- epilogue: silu + bias, vector red scatter into g_agg ----
    #pragma unroll
    for (int mf = 0; mf < 2; mf++) {
        #pragma unroll
        for (int rr = 0; rr < 2; rr++) {
            int m = wm*32 + mf*16 + (lane >> 2) + rr*8;
            float* ap = g_agg + (size_t)s_i[m]*DD;
            #pragma unroll
            for (int nf = 0; nf < 4; nf++) {
                int n = wn*32 + nf*8 + (lane & 3)*2;
                float v0 = silu_f(acc[mf][nf][rr*2 + 0] + eb2[n]);
                float v1 = silu_f(acc[mf][nf][rr*2 + 1] + eb2[n + 1]);
                asm volatile("red.global.add.v2.f32 [%0], {%1, %2};"
                             :: "l"(ap + n), "f"(v0), "f"(v1) : "memory");
            }
        }
    }
}

// ---------------- kernel 5: node MLP via tf32 mma, cp.async pipelined ----------------
#define TN 128
#define SA2 260    // 260%32=4 -> conflict-free frags

__global__ __launch_bounds__(512, 1)
void node_kernel(const float* __restrict__ nfeat,
                 const float* __restrict__ nw1, const float* __restrict__ nb1,
                 const float* __restrict__ nw2, const float* __restrict__ nb2,
                 float* __restrict__ out)
{
    extern __shared__ float sm[];
    float* s_a  = sm;              // TN*SA2
    float* s_bb = sm + TN*SA2;     // 2*BBF
    __shared__ float s_cnt[TN];

    int tid  = threadIdx.x;
    int lane = tid & 31;
    int wid  = tid >> 5;
    int wm = wid >> 2, wn = wid & 3;
    int n0 = blockIdx.x * TN;
    int brow = tid >> 5, bc4 = (tid & 31) * 4;

    if (tid < TN) {
        int n = min(n0 + tid, NN - 1);
        s_cnt[tid] = fmaxf((float)g_cnt[n], 1.f);
    }
    // async load h rows (cols 0..127)
    #pragma unroll
    for (int it = 0; it < 8; it++) {
        int idx = tid + it*512;
        int r = idx >> 5, c4 = (idx & 31) * 4;
        int n = min(n0 + r, NN - 1);
        cpa16(s_a + r*SA2 + c4, g_h + (size_t)n*DD + c4);
    }
    // nw1 chunk 0 -> buf0
    cpa16(s_bb + brow*SB + bc4, nw1 + (size_t)brow*DD + bc4);
    CP_COMMIT;
    __syncthreads();   // s_cnt visible

    // agg/cnt -> cols 128..255 (scalar path, divides)
    for (int it = 0; it < 8; it++) {
        int idx = tid + it*512;
        int r = idx >> 5, c4 = (idx & 31) * 4;
        int n = min(n0 + r, NN - 1);
        float inv = __fdividef(1.f, s_cnt[r]);
        float4 v = *(const float4*)(g_agg + (size_t)n*DD + c4);
        float* dst = s_a + r*SA2 + DD + c4;
        dst[0] = v.x * inv; dst[1] = v.y * inv; dst[2] = v.z * inv; dst[3] = v.w * inv;
    }

    float acc[2][4][4];
    #pragma unroll
    for (int mf = 0; mf < 2; mf++)
        #pragma unroll
        for (int nf = 0; nf < 4; nf++)
            #pragma unroll
            for (int u = 0; u < 4; u++) acc[mf][nf][u] = 0.f;

    CP_WAIT0;
    __syncthreads();

    // ---- GEMM1: [128,256] x nw1[256,128], 16 chunks ----
    for (int ct = 0; ct < 16; ct++) {
        if (ct < 15) {
            cpa16(s_bb + ((ct+1)&1)*BBF + brow*SB + bc4,
                  nw1 + (size_t)(ct*16 + 16 + brow)*DD + bc4);
        } else {
            cpa16(s_bb + ((ct+1)&1)*BBF + brow*SB + bc4,   // nw2 chunk0 -> buf0
                  nw2 + (size_t)brow*DD + bc4);
        }
        CP_COMMIT;
        const float* bB = s_bb + (ct & 1)*BBF;
        #pragma unroll
        for (int kk = 0; kk < 16; kk += 8) {
            int kg = ct*16 + kk;
            uint32_t afr[2][4];
            #pragma unroll
            for (int mf = 0; mf < 2; mf++) {
                const float* ap = s_a + (wm*32 + mf*16 + (lane >> 2))*SA2 + kg + (lane & 3);
                afr[mf][0] = __float_as_uint(ap[0]);
                afr[mf][1] = __float_as_uint(ap[8*SA2]);
                afr[mf][2] = __float_as_uint(ap[4]);
                afr[mf][3] = __float_as_uint(ap[8*SA2 + 4]);
            }
            uint32_t bfr[4][2];
            #pragma unroll
            for (int nf = 0; nf < 4; nf++) {
                const float* bp = bB + (kk + (lane & 3))*SB + wn*32 + nf*8 + (lane >> 2);
                bfr[nf][0] = __float_as_uint(bp[0]);
                bfr[nf][1] = __float_as_uint(bp[4*SB]);
            }
            #pragma unroll
            for (int mf = 0; mf < 2; mf++)
                #pragma unroll
                for (int nf = 0; nf < 4; nf++)
                    mma_tf32(acc[mf][nf], afr[mf], bfr[nf]);
        }
        CP_WAIT0;
        __syncthreads();
    }

    // hidden -> s_a cols 0..127
    #pragma unroll
    for (int mf = 0; mf < 2; mf++) {
        int r0 = wm*32 + mf*16 + (lane >> 2);
        #pragma unroll
        for (int nf = 0; nf < 4; nf++) {
            int n = wn*32 + nf*8 + (lane & 3)*2;
            float b0 = nb1[n], b1 = nb1[n + 1];
            s_a[r0*SA2 + n]           = silu_f(acc[mf][nf][0] + b0);
            s_a[r0*SA2 + n + 1]       = silu_f(acc[mf][nf][1] + b1);
            s_a[(r0 + 8)*SA2 + n]     = silu_f(acc[mf][nf][2] + b0);
            s_a[(r0 + 8)*SA2 + n + 1] = silu_f(acc[mf][nf][3] + b1);
            #pragma unroll
            for (int u = 0; u < 4; u++) acc[mf][nf][u] = 0.f;
        }
    }
    __syncthreads();

    // ---- GEMM2: [128,128] x nw2[128,128], 8 chunks; chunk c in buf[c&1] ----
    for (int c = 0; c < 8; c++) {
        if (c < 7) {
            cpa16(s_bb + ((c+1)&1)*BBF + brow*SB + bc4,
                  nw2 + (size_t)(c*16 + 16 + brow)*DD + bc4);
            CP_COMMIT;
        }
        const float* bB = s_bb + (c & 1)*BBF;
        #pragma unroll
        for (int kk = 0; kk < 16; kk += 8) {
            int kg = c*16 + kk;
            uint32_t afr[2][4];
            #pragma unroll
            for (int mf = 0; mf < 2; mf++) {
                const float* ap = s_a + (wm*32 + mf*16 + (lane >> 2))*SA2 + kg + (lane & 3);
                afr[mf][0] = __float_as_uint(ap[0]);
                afr[mf][1] = __float_as_uint(ap[8*SA2]);
                afr[mf][2] = __float_as_uint(ap[4]);
                afr[mf][3] = __float_as_uint(ap[8*SA2 + 4]);
            }
            uint32_t bfr[4][2];
            #pragma unroll
            for (int nf = 0; nf < 4; nf++) {
                const float* bp = bB + (kk + (lane & 3))*SB + wn*32 + nf*8 + (lane >> 2);
                bfr[nf][0] = __float_as_uint(bp[0]);
                bfr[nf][1] = __float_as_uint(bp[4*SB]);
            }
            #pragma unroll
            for (int mf = 0; mf < 2; mf++)
                #pragma unroll
                for (int nf = 0; nf < 4; nf++)
                    mma_tf32(acc[mf][nf], afr[mf], bfr[nf]);
        }
        if (c < 7) { CP_WAIT0; }
        __syncthreads();
    }

    // epilogue: out = nfeat + silu(acc + nb2)
    #pragma unroll
    for (int mf = 0; mf < 2; mf++) {
        #pragma unroll
        for (int rr = 0; rr < 2; rr++) {
            int m = wm*32 + mf*16 + (lane >> 2) + rr*8;
            int n = n0 + m;
            if (n < NN) {
                const float* nfr = nfeat + (size_t)n*DD;
                float* orow = out + (size_t)n*DD;
                #pragma unroll
                for (int nf = 0; nf < 4; nf++) {
                    int col = wn*32 + nf*8 + (lane & 3)*2;
                    orow[col]     = nfr[col]     + silu_f(acc[mf][nf][rr*2 + 0] + nb2[col]);
                    orow[col + 1] = nfr[col + 1] + silu_f(acc[mf][nf][rr*2 + 1] + nb2[col + 1]);
                }
            }
        }
    }
}

// ---------------- launch ----------------
extern "C" void kernel_launch(void* const* d_in, const int* in_sizes, int n_in,
                              void* d_out, int out_size)
{
    const float* node_features = (const float*)d_in[0];
    const float* cond = (const float*)d_in[1];
    const int*   n2g  = (const int*)d_in[2];
    const float* frac = (const float*)d_in[3];
    const float* lat  = (const float*)d_in[4];
    const int*   edges= (const int*)d_in[5];
    const int*   e2g  = (const int*)d_in[6];
    const float* wq = (const float*)d_in[7];
    const float* bq = (const float*)d_in[8];
    const float* wk = (const float*)d_in[9];
    const float* bk = (const float*)d_in[10];
    const float* wv = (const float*)d_in[11];
    const float* bv = (const float*)d_in[12];
    const float* wo = (const float*)d_in[13];
    const float* bo = (const float*)d_in[14];
    const float* sw1= (const float*)d_in[15];
    const float* sb1= (const float*)d_in[16];
    const float* sw2= (const float*)d_in[17];
    const float* sb2= (const float*)d_in[18];
    const float* ew1= (const float*)d_in[19];
    const float* eb1= (const float*)d_in[20];
    const float* ew2= (const float*)d_in[21];
    const float* eb2= (const float*)d_in[22];
    const float* nw1= (const float*)d_in[23];
    const float* nb1= (const float*)d_in[24];
    const float* nw2= (const float*)d_in[25];
    const float* nb2= (const float*)d_in[26];
    float* out = (float*)d_out;

    const int attn_smem = 39432 * 4;
    const int edge_smem = (TM*SA + 2*BBF) * 4;    // 158,720 B
    const int node_smem = (TN*SA2 + 2*BBF) * 4;   // 150,528 B
    cudaFuncSetAttribute(attn_kernel, cudaFuncAttributeMaxDynamicSharedMemorySize, attn_smem);
    cudaFuncSetAttribute(edge_kernel, cudaFuncAttributeMaxDynamicSharedMemorySize, edge_smem);
    cudaFuncSetAttribute(node_kernel, cudaFuncAttributeMaxDynamicSharedMemorySize, node_smem);

    prep_kernel<<<BB*TT + BB, 128>>>(cond, wk, bk, wv, bv, lat);
    zero_kernel<<<(NN*DD + 255) / 256, 256>>>();
    attn_kernel<<<152, 512, attn_smem>>>(node_features, frac, n2g,
                                         wq, bq, wo, bo, sw1, sb1, sw2, sb2);
    edge_kernel<<<EE / TM, 512, edge_smem>>>(frac, edges, e2g, ew1, eb1, ew2, eb2);
    node_kernel<<<(NN + TN - 1) / TN, 512, node_smem>>>(node_features, nw1, nb1, nw2, nb2, out);
}

// round 5
// speedup vs baseline: 1.4761x; 1.4761x over previous
#include <cuda_runtime.h>
#include <math.h>
#include <stdint.h>

#define NN 50000
#define EE 800000
#define BB 256
#define DD 128
#define TT 8
#define KV_OFF (BB*TT*DD)

// ---------------- scratch (no allocations allowed) ----------------
__device__ float g_h[(size_t)NN*DD];        // post-attention node states
__device__ float g_KV[2*BB*TT*DD];          // Kc then Vc
__device__ float g_lip[BB*9];               // lattice inner products
__device__ float g_agg[(size_t)NN*DD];      // scatter sums
__device__ int   g_cnt[NN];                 // scatter counts

__device__ __forceinline__ float silu_f(float x) {
    return __fdividef(x, 1.f + __expf(-x));
}

__device__ __forceinline__ void mma_tf32(float* c, const uint32_t* a, const uint32_t* b) {
    asm volatile(
        "mma.sync.aligned.m16n8k8.row.col.f32.tf32.tf32.f32 "
        "{%0,%1,%2,%3}, {%4,%5,%6,%7}, {%8,%9}, {%0,%1,%2,%3};\n"
        : "+f"(c[0]), "+f"(c[1]), "+f"(c[2]), "+f"(c[3])
        : "r"(a[0]), "r"(a[1]), "r"(a[2]), "r"(a[3]), "r"(b[0]), "r"(b[1]));
}

__device__ __forceinline__ void cpa16(float* dst, const float* src) {
    uint32_t d = (uint32_t)__cvta_generic_to_shared(dst);
    asm volatile("cp.async.cg.shared.global [%0], [%1], 16;" :: "r"(d), "l"(src));
}
#define CP_COMMIT asm volatile("cp.async.commit_group;" ::: "memory")
#define CP_WAIT0  asm volatile("cp.async.wait_group 0;" ::: "memory")

#define SB 136
#define BBF (16*SB)

// Fragment loads shared by all GEMMs (A stride = SAx)
#define LOAD_AFRAG(afr, s_a, SAx, rowbase, kg)                                   \
    {                                                                            \
        const float* ap_ = (s_a) + ((rowbase) + (lane >> 2))*(SAx) + (kg) + (lane & 3); \
        afr[0] = __float_as_uint(ap_[0]);                                        \
        afr[1] = __float_as_uint(ap_[8*(SAx)]);                                  \
        afr[2] = __float_as_uint(ap_[4]);                                        \
        afr[3] = __float_as_uint(ap_[8*(SAx) + 4]);                              \
    }
#define LOAD_BFRAG(bfr, bB, kk, ncol)                                            \
    {                                                                            \
        const float* bp_ = (bB) + ((kk) + (lane & 3))*SB + (ncol) + (lane >> 2); \
        bfr[0] = __float_as_uint(bp_[0]);                                        \
        bfr[1] = __float_as_uint(bp_[4*SB]);                                     \
    }

// ---------------- kernel 1: K/V projection + lattice gram ----------------
__global__ void prep_kernel(const float* __restrict__ cond,
                            const float* __restrict__ wk, const float* __restrict__ bk,
                            const float* __restrict__ wv, const float* __restrict__ bv,
                            const float* __restrict__ lat)
{
    int b = blockIdx.x;
    if (b < BB*TT) {
        __shared__ float s_c[DD];
        int d = threadIdx.x;
        s_c[d] = cond[b*DD + d];
        __syncthreads();
        float ka = bk[d], va = bv[d];
        #pragma unroll 8
        for (int k = 0; k < DD; k++) {
            float c = s_c[k];
            ka = fmaf(c, wk[k*DD + d], ka);
            va = fmaf(c, wv[k*DD + d], va);
        }
        g_KV[b*DD + d] = ka;
        g_KV[KV_OFF + b*DD + d] = va;
    } else {
        int bb = b - BB*TT;
        int t = threadIdx.x;
        if (t < 9) {
            int i = t / 3, k2 = t % 3;
            const float* L = lat + bb*9;
            g_lip[bb*9 + t] = L[i*3+0]*L[k2*3+0] + L[i*3+1]*L[k2*3+1] + L[i*3+2]*L[k2*3+2];
        }
    }
}

// ---------------- kernel 2: zero scatter buffers ----------------
__global__ void zero_kernel()
{
    int idx = blockIdx.x * blockDim.x + threadIdx.x;
    if (idx < NN*DD) g_agg[idx] = 0.f;
    if (idx < NN)    g_cnt[idx] = 0;
}

// ---------------- kernel 3: cross-attention, tf32 mma for Q/out proj ----------------
// Tile: 64 nodes, 256 threads (8 warps 2x4, warp tile 32x32), 2 CTAs/SM.
#define AT 64
#define SAH 132    // 132%32=4 -> conflict-free frags

__global__ __launch_bounds__(256, 2)
void attn_kernel(const float* __restrict__ nfeat, const float* __restrict__ frac,
                 const int* __restrict__ n2g,
                 const float* __restrict__ wq, const float* __restrict__ bq,
                 const float* __restrict__ wo, const float* __restrict__ bo,
                 const float* __restrict__ sw1, const float* __restrict__ sb1,
                 const float* __restrict__ sw2, const float* __restrict__ sb2)
{
    extern __shared__ float sm[];
    float* s_h   = sm;                  // AT*SAH (h tile, A of GEMM1)
    float* s_q   = s_h + AT*SAH;        // AT*SAH (Q, later ca)
    float* s_bb  = s_q + AT*SAH;        // 2*BBF
    float* s_sw1 = s_bb + 2*BBF;        // 3072
    float* s_sw2 = s_sw1 + 3072;        // 1024
    float* s_sb1 = s_sw2 + 1024;        // 128
    float* s_sb2 = s_sb1 + 128;         // 8
    float* s_enc = s_sb2 + 8;           // AT*24
    float* s_att = s_enc + AT*24;       // AT*8
    __shared__ int s_g[AT];

    int tid = threadIdx.x, lane = tid & 31, wid = tid >> 5;
    int wm = wid >> 2, wn = wid & 3;
    int n0 = blockIdx.x * AT;
    int brow = tid >> 5, bc4 = (tid & 31) * 4;

    if (tid < AT) s_g[tid] = n2g[min(n0 + tid, NN - 1)];

    // async loads: h tile, small weights, wq chunk0
    #pragma unroll
    for (int it = 0; it < 8; it++) {
        int idx = tid + it*256;
        int r = idx >> 5, c4 = (idx & 31) * 4;
        int n = min(n0 + r, NN - 1);
        cpa16(s_h + r*SAH + c4, nfeat + (size_t)n*DD + c4);
    }
    #pragma unroll
    for (int it = 0; it < 3; it++) {
        int idx = tid + it*256;
        cpa16(s_sw1 + idx*4, sw1 + idx*4);
    }
    cpa16(s_sw2 + tid*4, sw2 + tid*4);
    if (tid < 32) cpa16(s_sb1 + tid*4, sb1 + tid*4);
    if (tid < 2)  cpa16(s_sb2 + tid*4, sb2 + tid*4);
    cpa16(s_bb + brow*SB + bc4, wq + (size_t)brow*DD + bc4);
    cpa16(s_bb + (brow+8)*SB + bc4, wq + (size_t)(brow+8)*DD + bc4);
    CP_COMMIT;

    // enc (scalar, overlaps cp.async flight)
    {
        int n = tid >> 2, sub = tid & 3;
        int nn = min(n0 + n, NN - 1);
        float f0 = frac[nn*3+0], f1 = frac[nn*3+1], f2 = frac[nn*3+2];
        #pragma unroll
        for (int k = sub; k < 24; k += 4) {
            int ii = k % 12, c = ii >> 2, j = ii & 3;
            float fv = (c == 0) ? f0 : ((c == 1) ? f1 : f2);
            float ph = fv * ((float)(1 << j) * 3.14159265358979323846f);
            s_enc[n*24 + k] = (k < 12) ? sinf(ph) : cosf(ph);
        }
    }
    CP_WAIT0;
    __syncthreads();

    float acc[2][4][4];
    #pragma unroll
    for (int mf = 0; mf < 2; mf++)
        #pragma unroll
        for (int nf = 0; nf < 4; nf++)
            #pragma unroll
            for (int u = 0; u < 4; u++) acc[mf][nf][u] = 0.f;

    // ---- GEMM1: Q = h @ wq, 8 chunks ----
    for (int ct = 0; ct < 8; ct++) {
        const float* wsrc = (ct < 7) ? (wq + (size_t)(ct*16 + 16)*DD) : wo;
        float* dbuf = s_bb + ((ct+1)&1)*BBF;
        cpa16(dbuf + brow*SB + bc4, wsrc + (size_t)brow*DD + bc4);
        cpa16(dbuf + (brow+8)*SB + bc4, wsrc + (size_t)(brow+8)*DD + bc4);
        CP_COMMIT;
        const float* bB = s_bb + (ct & 1)*BBF;
        #pragma unroll
        for (int kk = 0; kk < 16; kk += 8) {
            int kg = ct*16 + kk;
            uint32_t afr[2][4];
            #pragma unroll
            for (int mf = 0; mf < 2; mf++) LOAD_AFRAG(afr[mf], s_h, SAH, wm*32 + mf*16, kg);
            uint32_t bfr[4][2];
            #pragma unroll
            for (int nf = 0; nf < 4; nf++) LOAD_BFRAG(bfr[nf], bB, kk, wn*32 + nf*8);
            #pragma unroll
            for (int mf = 0; mf < 2; mf++)
                #pragma unroll
                for (int nf = 0; nf < 4; nf++)
                    mma_tf32(acc[mf][nf], afr[mf], bfr[nf]);
        }
        CP_WAIT0;
        __syncthreads();
    }
    // Q -> s_q (+bq)
    #pragma unroll
    for (int mf = 0; mf < 2; mf++) {
        int r0 = wm*32 + mf*16 + (lane >> 2);
        #pragma unroll
        for (int nf = 0; nf < 4; nf++) {
            int n = wn*32 + nf*8 + (lane & 3)*2;
            float b0 = bq[n], b1 = bq[n + 1];
            s_q[r0*SAH + n]           = acc[mf][nf][0] + b0;
            s_q[r0*SAH + n + 1]       = acc[mf][nf][1] + b1;
            s_q[(r0 + 8)*SAH + n]     = acc[mf][nf][2] + b0;
            s_q[(r0 + 8)*SAH + n + 1] = acc[mf][nf][3] + b1;
            #pragma unroll
            for (int u = 0; u < 4; u++) acc[mf][nf][u] = 0.f;
        }
    }
    __syncthreads();

    // ---- bias MLP + scores + softmax (thread = (node, sub), 4 lanes per node) ----
    {
        int n = tid >> 2, sub = tid & 3;
        int gg = s_g[n];
        float b8[8];
        #pragma unroll
        for (int t = 0; t < 8; t++) b8[t] = 0.f;
        const float* en = s_enc + n*24;
        for (int cc = 0; cc < 32; cc++) {
            int c = cc*4 + sub;
            float hid = s_sb1[c];
            #pragma unroll
            for (int k = 0; k < 24; k++) hid = fmaf(en[k], s_sw1[k*DD + c], hid);
            hid = silu_f(hid);
            #pragma unroll
            for (int t = 0; t < 8; t++) b8[t] = fmaf(hid, s_sw2[c*8 + t], b8[t]);
        }
        #pragma unroll
        for (int t = 0; t < 8; t++) {
            b8[t] += __shfl_xor_sync(0xffffffffu, b8[t], 1, 4);
            b8[t] += __shfl_xor_sync(0xffffffffu, b8[t], 2, 4);
        }
        int t0 = sub*2, t1 = t0 + 1;
        const float* K0 = g_KV + (size_t)(gg*TT + t0)*DD;
        const float* K1 = K0 + DD;
        const float* qq = s_q + n*SAH;
        float sc0 = 0.f, sc1 = 0.f;
        #pragma unroll 8
        for (int k = 0; k < DD; k++) {
            float qv = qq[k];
            sc0 = fmaf(qv, K0[k], sc0);
            sc1 = fmaf(qv, K1[k], sc1);
        }
        float v0 = sc0 * 0.08838834764831845f + b8[t0] + s_sb2[t0];
        float v1 = sc1 * 0.08838834764831845f + b8[t1] + s_sb2[t1];
        float m = fmaxf(v0, v1);
        m = fmaxf(m, __shfl_xor_sync(0xffffffffu, m, 1, 4));
        m = fmaxf(m, __shfl_xor_sync(0xffffffffu, m, 2, 4));
        float e0 = __expf(v0 - m), e1 = __expf(v1 - m);
        float s = e0 + e1;
        s += __shfl_xor_sync(0xffffffffu, s, 1, 4);
        s += __shfl_xor_sync(0xffffffffu, s, 2, 4);
        float inv = __fdividef(1.f, s);
        s_att[n*8 + t0] = e0 * inv;
        s_att[n*8 + t1] = e1 * inv;
    }
    __syncthreads();

    // ---- ca = attn @ V -> s_q ----
    #pragma unroll
    for (int it = 0; it < 32; it++) {
        int idx = tid + it*256;
        int n = idx >> 7, c = idx & 127;
        const float* Vr = g_KV + KV_OFF + (size_t)s_g[n]*TT*DD + c;
        const float* at = s_att + n*8;
        float a = 0.f;
        #pragma unroll
        for (int t = 0; t < 8; t++) a = fmaf(at[t], Vr[t*DD], a);
        s_q[n*SAH + c] = a;
    }
    __syncthreads();

    // ---- GEMM2: out = ca @ wo (chunk0 already in buf0) ----
    for (int c = 0; c < 8; c++) {
        if (c < 7) {
            float* dbuf = s_bb + ((c+1)&1)*BBF;
            cpa16(dbuf + brow*SB + bc4, wo + (size_t)(c*16 + 16 + brow)*DD + bc4);
            cpa16(dbuf + (brow+8)*SB + bc4, wo + (size_t)(c*16 + 24 + brow)*DD + bc4);
            CP_COMMIT;
        }
        const float* bB = s_bb + (c & 1)*BBF;
        #pragma unroll
        for (int kk = 0; kk < 16; kk += 8) {
            int kg = c*16 + kk;
            uint32_t afr[2][4];
            #pragma unroll
            for (int mf = 0; mf < 2; mf++) LOAD_AFRAG(afr[mf], s_q, SAH, wm*32 + mf*16, kg);
            uint32_t bfr[4][2];
            #pragma unroll
            for (int nf = 0; nf < 4; nf++) LOAD_BFRAG(bfr[nf], bB, kk, wn*32 + nf*8);
            #pragma unroll
            for (int mf = 0; mf < 2; mf++)
                #pragma unroll
                for (int nf = 0; nf < 4; nf++)
                    mma_tf32(acc[mf][nf], afr[mf], bfr[nf]);
        }
        if (c < 7) { CP_WAIT0; }
        __syncthreads();
    }

    // epilogue: g_h = h + ca@wo + bo
    #pragma unroll
    for (int mf = 0; mf < 2; mf++) {
        #pragma unroll
        for (int rr = 0; rr < 2; rr++) {
            int m = wm*32 + mf*16 + (lane >> 2) + rr*8;
            int n = n0 + m;
            if (n < NN) {
                float* orow = g_h + (size_t)n*DD;
                const float* hrow = s_h + m*SAH;
                #pragma unroll
                for (int nf = 0; nf < 4; nf++) {
                    int col = wn*32 + nf*8 + (lane & 3)*2;
                    orow[col]     = hrow[col]     + acc[mf][nf][rr*2 + 0] + bo[col];
                    orow[col + 1] = hrow[col + 1] + acc[mf][nf][rr*2 + 1] + bo[col + 1];
                }
            }
        }
    }
}

// ---------------- kernel 4: edge MLP, 64-edge tiles, 2 CTAs/SM ----------------
#define TM 64
#define SA 276     // 276%32=20 -> conflict-free frags

__global__ __launch_bounds__(256, 2)
void edge_kernel(const float* __restrict__ frac,
                 const int* __restrict__ edges, const int* __restrict__ e2g,
                 const float* __restrict__ ew1, const float* __restrict__ eb1,
                 const float* __restrict__ ew2, const float* __restrict__ eb2)
{
    extern __shared__ float sm[];
    float* s_a  = sm;             // TM*SA
    float* s_bb = sm + TM*SA;     // 2*BBF
    __shared__ int s_i[TM], s_j[TM];

    int tid  = threadIdx.x, lane = tid & 31, wid = tid >> 5;
    int wm = wid >> 2, wn = wid & 3;
    int e0 = blockIdx.x * TM;
    int brow = tid >> 5, bc4 = (tid & 31) * 4;

    if (tid < TM) {
        s_i[tid] = edges[e0 + tid];
        s_j[tid] = edges[EE + e0 + tid];
    }
    __syncthreads();

    // async gather A
    #pragma unroll
    for (int it = 0; it < 16; it++) {
        int idx = tid + it*256;
        int r = idx >> 5, c4 = (idx & 31) * 4;
        int e = r >> 1, p = r & 1;
        int node = p ? s_j[e] : s_i[e];
        cpa16(s_a + e*SA + p*DD + c4, g_h + (size_t)node*DD + c4);
    }
    cpa16(s_bb + brow*SB + bc4, ew1 + (size_t)brow*DD + bc4);
    cpa16(s_bb + (brow+8)*SB + bc4, ew1 + (size_t)(brow+8)*DD + bc4);
    CP_COMMIT;

    if (tid < TM) {
        int e = tid;
        const float* lp = g_lip + e2g[e0 + e]*9;
        #pragma unroll
        for (int u = 0; u < 9; u++) s_a[e*SA + 256 + u] = lp[u];
        int ii = s_i[e], jj = s_j[e];
        #pragma unroll
        for (int c = 0; c < 3; c++) {
            float dd = frac[jj*3 + c] - frac[ii*3 + c];
            dd -= floorf(dd);
            s_a[e*SA + 265 + c] = dd;
        }
        #pragma unroll
        for (int u = 268; u < 276; u++) s_a[e*SA + u] = 0.f;
        atomicAdd(&g_cnt[ii], 1);
    }

    float acc[2][4][4];
    #pragma unroll
    for (int mf = 0; mf < 2; mf++)
        #pragma unroll
        for (int nf = 0; nf < 4; nf++)
            #pragma unroll
            for (int u = 0; u < 4; u++) acc[mf][nf][u] = 0.f;

    CP_WAIT0;
    __syncthreads();

    // ---- GEMM1: 17 chunks (k=272, rows >=268 clamp to 267, A zero there) ----
    for (int ct = 0; ct < 17; ct++) {
        float* dbuf = s_bb + ((ct+1)&1)*BBF;
        if (ct < 16) {
            int kr0 = min(ct*16 + 16 + brow, 267);
            int kr1 = min(ct*16 + 24 + brow, 267);
            cpa16(dbuf + brow*SB + bc4, ew1 + (size_t)kr0*DD + bc4);
            cpa16(dbuf + (brow+8)*SB + bc4, ew1 + (size_t)kr1*DD + bc4);
        } else {
            cpa16(dbuf + brow*SB + bc4, ew2 + (size_t)brow*DD + bc4);
            cpa16(dbuf + (brow+8)*SB + bc4, ew2 + (size_t)(brow+8)*DD + bc4);
        }
        CP_COMMIT;
        const float* bB = s_bb + (ct & 1)*BBF;
        #pragma unroll
        for (int kk = 0; kk < 16; kk += 8) {
            int kg = ct*16 + kk;
            uint32_t afr[2][4];
            #pragma unroll
            for (int mf = 0; mf < 2; mf++) LOAD_AFRAG(afr[mf], s_a, SA, wm*32 + mf*16, kg);
            uint32_t bfr[4][2];
            #pragma unroll
            for (int nf = 0; nf < 4; nf++) LOAD_BFRAG(bfr[nf], bB, kk, wn*32 + nf*8);
            #pragma unroll
            for (int mf = 0; mf < 2; mf++)
                #pragma unroll
                for (int nf = 0; nf < 4; nf++)
                    mma_tf32(acc[mf][nf], afr[mf], bfr[nf]);
        }
        CP_WAIT0;
        __syncthreads();
    }

    // hidden = silu(acc + eb1) -> s_a cols 0..127
    #pragma unroll
    for (int mf = 0; mf < 2; mf++) {
        int r0 = wm*32 + mf*16 + (lane >> 2);
        #pragma unroll
        for (int nf = 0; nf < 4; nf++) {
            int n = wn*32 + nf*8 + (lane & 3)*2;
            float b0 = eb1[n], b1 = eb1[n + 1];
            s_a[r0*SA + n]           = silu_f(acc[mf][nf][0] + b0);
            s_a[r0*SA + n + 1]       = silu_f(acc[mf][nf][1] + b1);
            s_a[(r0 + 8)*SA + n]     = silu_f(acc[mf][nf][2] + b0);
            s_a[(r0 + 8)*SA + n + 1] = silu_f(acc[mf][nf][3] + b1);
            #pragma unroll
            for (int u = 0; u < 4; u++) acc[mf][nf][u] = 0.f;
        }
    }
    __syncthreads();

    // ---- GEMM2: 8 chunks ew2; chunk c in buf[(1+c)&1] ----
    for (int c = 0; c < 8; c++) {
        if (c < 7) {
            float* dbuf = s_bb + (c & 1)*BBF;
            cpa16(dbuf + brow*SB + bc4, ew2 + (size_t)(c*16 + 16 + brow)*DD + bc4);
            cpa16(dbuf + (brow+8)*SB + bc4, ew2 + (size_t)(c*16 + 24 + brow)*DD + bc4);
            CP_COMMIT;
        }
        const float* bB = s_bb + ((1 + c) & 1)*BBF;
        #pragma unroll
        for (int kk = 0; kk < 16; kk += 8) {
            int kg = c*16 + kk;
            uint32_t afr[2][4];
            #pragma unroll
            for (int mf = 0; mf < 2; mf++) LOAD_AFRAG(afr[mf], s_a, SA, wm*32 + mf*16, kg);
            uint32_t bfr[4][2];
            #pragma unroll
            for (int nf = 0; nf < 4; nf++) LOAD_BFRAG(bfr[nf], bB, kk, wn*32 + nf*8);
            #pragma unroll
            for (int mf = 0; mf < 2; mf++)
                #pragma unroll
                for (int nf = 0; nf < 4; nf++)
                    mma_tf32(acc[mf][nf], afr[mf], bfr[nf]);
        }
        if (c < 7) { CP_WAIT0; }
        __syncthreads();
    }

    // epilogue: silu + bias, red.v2 scatter
    #pragma unroll
    for (int mf = 0; mf < 2; mf++) {
        #pragma unroll
        for (int rr = 0; rr < 2; rr++) {
            int m = wm*32 + mf*16 + (lane >> 2) + rr*8;
            float* ap = g_agg + (size_t)s_i[m]*DD;
            #pragma unroll
            for (int nf = 0; nf < 4; nf++) {
                int n = wn*32 + nf*8 + (lane & 3)*2;
                float v0 = silu_f(acc[mf][nf][rr*2 + 0] + eb2[n]);
                float v1 = silu_f(acc[mf][nf][rr*2 + 1] + eb2[n + 1]);
                asm volatile("red.global.add.v2.f32 [%0], {%1, %2};"
                             :: "l"(ap + n), "f"(v0), "f"(v1) : "memory");
            }
        }
    }
}

// ---------------- kernel 5: node MLP, 64-node tiles, 2 CTAs/SM ----------------
#define TN 64
#define SA2 260    // 260%32=4 -> conflict-free frags

__global__ __launch_bounds__(256, 2)
void node_kernel(const float* __restrict__ nfeat,
                 const float* __restrict__ nw1, const float* __restrict__ nb1,
                 const float* __restrict__ nw2, const float* __restrict__ nb2,
                 float* __restrict__ out)
{
    extern __shared__ float sm[];
    float* s_a  = sm;              // TN*SA2
    float* s_bb = sm + TN*SA2;     // 2*BBF
    __shared__ float s_cnt[TN];

    int tid  = threadIdx.x, lane = tid & 31, wid = tid >> 5;
    int wm = wid >> 2, wn = wid & 3;
    int n0 = blockIdx.x * TN;
    int brow = tid >> 5, bc4 = (tid & 31) * 4;

    if (tid < TN) {
        int n = min(n0 + tid, NN - 1);
        s_cnt[tid] = fmaxf((float)g_cnt[n], 1.f);
    }
    #pragma unroll
    for (int it = 0; it < 8; it++) {
        int idx = tid + it*256;
        int r = idx >> 5, c4 = (idx & 31) * 4;
        int n = min(n0 + r, NN - 1);
        cpa16(s_a + r*SA2 + c4, g_h + (size_t)n*DD + c4);
    }
    cpa16(s_bb + brow*SB + bc4, nw1 + (size_t)brow*DD + bc4);
    cpa16(s_bb + (brow+8)*SB + bc4, nw1 + (size_t)(brow+8)*DD + bc4);
    CP_COMMIT;
    __syncthreads();   // s_cnt visible

    #pragma unroll
    for (int it = 0; it < 8; it++) {
        int idx = tid + it*256;
        int r = idx >> 5, c4 = (idx & 31) * 4;
        int n = min(n0 + r, NN - 1);
        float inv = __fdividef(1.f, s_cnt[r]);
        float4 v = *(const float4*)(g_agg + (size_t)n*DD + c4);
        float* dst = s_a + r*SA2 + DD + c4;
        dst[0] = v.x * inv; dst[1] = v.y * inv; dst[2] = v.z * inv; dst[3] = v.w * inv;
    }

    float acc[2][4][4];
    #pragma unroll
    for (int mf = 0; mf < 2; mf++)
        #pragma unroll
        for (int nf = 0; nf < 4; nf++)
            #pragma unroll
            for (int u = 0; u < 4; u++) acc[mf][nf][u] = 0.f;

    CP_WAIT0;
    __syncthreads();

    // ---- GEMM1: [64,256] x nw1, 16 chunks ----
    for (int ct = 0; ct < 16; ct++) {
        const float* wsrc = (ct < 15) ? (nw1 + (size_t)(ct*16 + 16)*DD) : nw2;
        float* dbuf = s_bb + ((ct+1)&1)*BBF;
        cpa16(dbuf + brow*SB + bc4, wsrc + (size_t)brow*DD + bc4);
        cpa16(dbuf + (brow+8)*SB + bc4, wsrc + (size_t)(brow+8)*DD + bc4);
        CP_COMMIT;
        const float* bB = s_bb + (ct & 1)*BBF;
        #pragma unroll
        for (int kk = 0; kk < 16; kk += 8) {
            int kg = ct*16 + kk;
            uint32_t afr[2][4];
            #pragma unroll
            for (int mf = 0; mf < 2; mf++) LOAD_AFRAG(afr[mf], s_a, SA2, wm*32 + mf*16, kg);
            uint32_t bfr[4][2];
            #pragma unroll
            for (int nf = 0; nf < 4; nf++) LOAD_BFRAG(bfr[nf], bB, kk, wn*32 + nf*8);
            #pragma unroll
            for (int mf = 0; mf < 2; mf++)
                #pragma unroll
                for (int nf = 0; nf < 4; nf++)
                    mma_tf32(acc[mf][nf], afr[mf], bfr[nf]);
        }
        CP_WAIT0;
        __syncthreads();
    }

    // hidden -> s_a cols 0..127
    #pragma unroll
    for (int mf = 0; mf < 2; mf++) {
        int r0 = wm*32 + mf*16 + (lane >> 2);
        #pragma unroll
        for (int nf = 0; nf < 4; nf++) {
            int n = wn*32 + nf*8 + (lane & 3)*2;
            float b0 = nb1[n], b1 = nb1[n + 1];
            s_a[r0*SA2 + n]           = silu_f(acc[mf][nf][0] + b0);
            s_a[r0*SA2 + n + 1]       = silu_f(acc[mf][nf][1] + b1);
            s_a[(r0 + 8)*SA2 + n]     = silu_f(acc[mf][nf][2] + b0);
            s_a[(r0 + 8)*SA2 + n + 1] = silu_f(acc[mf][nf][3] + b1);
            #pragma unroll
            for (int u = 0; u < 4; u++) acc[mf][nf][u] = 0.f;
        }
    }
    __syncthreads();

    // ---- GEMM2: nw2, 8 chunks; chunk c in buf[c&1] ----
    for (int c = 0; c < 8; c++) {
        if (c < 7) {
            float* dbuf = s_bb + ((c+1)&1)*BBF;
            cpa16(dbuf + brow*SB + bc4, nw2 + (size_t)(c*16 + 16 + brow)*DD + bc4);
            cpa16(dbuf + (brow+8)*SB + bc4, nw2 + (size_t)(c*16 + 24 + brow)*DD + bc4);
            CP_COMMIT;
        }
        const float* bB = s_bb + (c & 1)*BBF;
        #pragma unroll
        for (int kk = 0; kk < 16; kk += 8) {
            int kg = c*16 + kk;
            uint32_t afr[2][4];
            #pragma unroll
            for (int mf = 0; mf < 2; mf++) LOAD_AFRAG(afr[mf], s_a, SA2, wm*32 + mf*16, kg);
            uint32_t bfr[4][2];
            #pragma unroll
            for (int nf = 0; nf < 4; nf++) LOAD_BFRAG(bfr[nf], bB, kk, wn*32 + nf*8);
            #pragma unroll
            for (int mf = 0; mf < 2; mf++)
                #pragma unroll
                for (int nf = 0; nf < 4; nf++)
                    mma_tf32(acc[mf][nf], afr[mf], bfr[nf]);
        }
        if (c < 7) { CP_WAIT0; }
        __syncthreads();
    }

    // epilogue: out = nfeat + silu(acc + nb2)
    #pragma unroll
    for (int mf = 0; mf < 2; mf++) {
        #pragma unroll
        for (int rr = 0; rr < 2; rr++) {
            int m = wm*32 + mf*16 + (lane >> 2) + rr*8;
            int n = n0 + m;
            if (n < NN) {
                const float* nfr = nfeat + (size_t)n*DD;
                float* orow = out + (size_t)n*DD;
                #pragma unroll
                for (int nf = 0; nf < 4; nf++) {
                    int col = wn*32 + nf*8 + (lane & 3)*2;
                    orow[col]     = nfr[col]     + silu_f(acc[mf][nf][rr*2 + 0] + nb2[col]);
                    orow[col + 1] = nfr[col + 1] + silu_f(acc[mf][nf][rr*2 + 1] + nb2[col + 1]);
                }
            }
        }
    }
}

// ---------------- launch ----------------
extern "C" void kernel_launch(void* const* d_in, const int* in_sizes, int n_in,
                              void* d_out, int out_size)
{
    const float* node_features = (const float*)d_in[0];
    const float* cond = (const float*)d_in[1];
    const int*   n2g  = (const int*)d_in[2];
    const float* frac = (const float*)d_in[3];
    const float* lat  = (const float*)d_in[4];
    const int*   edges= (const int*)d_in[5];
    const int*   e2g  = (const int*)d_in[6];
    const float* wq = (const float*)d_in[7];
    const float* bq = (const float*)d_in[8];
    const float* wk = (const float*)d_in[9];
    const float* bk = (const float*)d_in[10];
    const float* wv = (const float*)d_in[11];
    const float* bv = (const float*)d_in[12];
    const float* wo = (const float*)d_in[13];
    const float* bo = (const float*)d_in[14];
    const float* sw1= (const float*)d_in[15];
    const float* sb1= (const float*)d_in[16];
    const float* sw2= (const float*)d_in[17];
    const float* sb2= (const float*)d_in[18];
    const float* ew1= (const float*)d_in[19];
    const float* eb1= (const float*)d_in[20];
    const float* ew2= (const float*)d_in[21];
    const float* eb2= (const float*)d_in[22];
    const float* nw1= (const float*)d_in[23];
    const float* nb1= (const float*)d_in[24];
    const float* nw2= (const float*)d_in[25];
    const float* nb2= (const float*)d_in[26];
    float* out = (float*)d_out;

    const int attn_smem = (2*AT*SAH + 2*BBF + 3072 + 1024 + 128 + 8 + AT*24 + AT*8) * 4;
    const int edge_smem = (TM*SA + 2*BBF) * 4;
    const int node_smem = (TN*SA2 + 2*BBF) * 4;
    cudaFuncSetAttribute(attn_kernel, cudaFuncAttributeMaxDynamicSharedMemorySize, attn_smem);
    cudaFuncSetAttribute(edge_kernel, cudaFuncAttributeMaxDynamicSharedMemorySize, edge_smem);
    cudaFuncSetAttribute(node_kernel, cudaFuncAttributeMaxDynamicSharedMemorySize, node_smem);

    prep_kernel<<<BB*TT + BB, 128>>>(cond, wk, bk, wv, bv, lat);
    zero_kernel<<<(NN*DD + 255) / 256, 256>>>();
    attn_kernel<<<(NN + AT - 1) / AT, 256, attn_smem>>>(node_features, frac, n2g,
                                                        wq, bq, wo, bo, sw1, sb1, sw2, sb2);
    edge_kernel<<<EE / TM, 256, edge_smem>>>(frac, edges, e2g, ew1, eb1, ew2, eb2);
    node_kernel<<<(NN + TN - 1) / TN, 256, node_smem>>>(node_features, nw1, nb1, nw2, nb2, out);
}

// round 6
// speedup vs baseline: 2.3053x; 1.5618x over previous
#include <cuda_runtime.h>
#include <cuda_fp16.h>
#include <math.h>
#include <stdint.h>

#define NN 50000
#define EE 800000
#define BB 256
#define DD 128
#define TT 8
#define KV_OFF (BB*TT*DD)

// ---------------- scratch (no allocations allowed) ----------------
__device__ __half g_h16[(size_t)NN*DD];     // post-attention node states (fp16)
__device__ float  g_KV[2*BB*TT*DD];         // Kc then Vc (fp32)
__device__ float  g_lip[BB*9];              // lattice inner products
__device__ float  g_agg[(size_t)NN*DD];     // scatter sums (fp32 atomics)
__device__ int    g_cnt[NN];                // scatter counts
// pre-converted, pre-transposed fp16 weights [N][K]
__device__ __half g_ew1T[DD*272];
__device__ __half g_ew2T[DD*DD];
__device__ __half g_nw1T[DD*256];
__device__ __half g_nw2T[DD*DD];

__device__ __forceinline__ float silu_f(float x) {
    return __fdividef(x, 1.f + __expf(-x));
}

// tf32 mma (attention kernel only)
__device__ __forceinline__ void mma_tf32(float* c, const uint32_t* a, const uint32_t* b) {
    asm volatile(
        "mma.sync.aligned.m16n8k8.row.col.f32.tf32.tf32.f32 "
        "{%0,%1,%2,%3}, {%4,%5,%6,%7}, {%8,%9}, {%0,%1,%2,%3};\n"
        : "+f"(c[0]), "+f"(c[1]), "+f"(c[2]), "+f"(c[3])
        : "r"(a[0]), "r"(a[1]), "r"(a[2]), "r"(a[3]), "r"(b[0]), "r"(b[1]));
}
// fp16 mma, fp32 accumulate
__device__ __forceinline__ void mma_f16(float* c, const uint32_t* a, const uint32_t* b) {
    asm volatile(
        "mma.sync.aligned.m16n8k16.row.col.f32.f16.f16.f32 "
        "{%0,%1,%2,%3}, {%4,%5,%6,%7}, {%8,%9}, {%0,%1,%2,%3};\n"
        : "+f"(c[0]), "+f"(c[1]), "+f"(c[2]), "+f"(c[3])
        : "r"(a[0]), "r"(a[1]), "r"(a[2]), "r"(a[3]), "r"(b[0]), "r"(b[1]));
}

__device__ __forceinline__ void cpa16(void* dst, const void* src) {
    uint32_t d = (uint32_t)__cvta_generic_to_shared(dst);
    asm volatile("cp.async.cg.shared.global [%0], [%1], 16;" :: "r"(d), "l"(src));
}
#define CP_COMMIT asm volatile("cp.async.commit_group;" ::: "memory")
#define CP_WAIT0  asm volatile("cp.async.wait_group 0;" ::: "memory")

// -------- fp16 fragment loads (A row-major [m][k], B as [n][k]) --------
#define LDA16(afr, base, SAx, rowbase, kg)                                        \
    {                                                                             \
        const __half* ap_ = (base) + ((rowbase) + (lane >> 2))*(SAx) + (kg) + ((lane & 3)*2); \
        afr[0] = *(const uint32_t*)(ap_);                                         \
        afr[1] = *(const uint32_t*)(ap_ + 8*(SAx));                               \
        afr[2] = *(const uint32_t*)(ap_ + 8);                                     \
        afr[3] = *(const uint32_t*)(ap_ + 8*(SAx) + 8);                           \
    }
#define LDB16(bfr, bB, SBx, ncol)                                                 \
    {                                                                             \
        const __half* bp_ = (bB) + ((ncol) + (lane >> 2))*(SBx) + ((lane & 3)*2); \
        bfr[0] = *(const uint32_t*)(bp_);                                         \
        bfr[1] = *(const uint32_t*)(bp_ + 8);                                     \
    }

// tf32 frag loads (attn)
#define SB 136
#define BBF (16*SB)
#define LOAD_AFRAG(afr, s_a, SAx, rowbase, kg)                                   \
    {                                                                            \
        const float* ap_ = (s_a) + ((rowbase) + (lane >> 2))*(SAx) + (kg) + (lane & 3); \
        afr[0] = __float_as_uint(ap_[0]);                                        \
        afr[1] = __float_as_uint(ap_[8*(SAx)]);                                  \
        afr[2] = __float_as_uint(ap_[4]);                                        \
        afr[3] = __float_as_uint(ap_[8*(SAx) + 4]);                              \
    }
#define LOAD_BFRAG(bfr, bB, kk, ncol)                                            \
    {                                                                            \
        const float* bp_ = (bB) + ((kk) + (lane & 3))*SB + (ncol) + (lane >> 2); \
        bfr[0] = __float_as_uint(bp_[0]);                                        \
        bfr[1] = __float_as_uint(bp_[4*SB]);                                     \
    }

// ---------------- kernel 1: K/V projection + lattice gram ----------------
__global__ void prep_kernel(const float* __restrict__ cond,
                            const float* __restrict__ wk, const float* __restrict__ bk,
                            const float* __restrict__ wv, const float* __restrict__ bv,
                            const float* __restrict__ lat)
{
    int b = blockIdx.x;
    if (b < BB*TT) {
        __shared__ float s_c[DD];
        int d = threadIdx.x;
        s_c[d] = cond[b*DD + d];
        __syncthreads();
        float ka = bk[d], va = bv[d];
        #pragma unroll 8
        for (int k = 0; k < DD; k++) {
            float c = s_c[k];
            ka = fmaf(c, wk[k*DD + d], ka);
            va = fmaf(c, wv[k*DD + d], va);
        }
        g_KV[b*DD + d] = ka;
        g_KV[KV_OFF + b*DD + d] = va;
    } else {
        int bb = b - BB*TT;
        int t = threadIdx.x;
        if (t < 9) {
            int i = t / 3, k2 = t % 3;
            const float* L = lat + bb*9;
            g_lip[bb*9 + t] = L[i*3+0]*L[k2*3+0] + L[i*3+1]*L[k2*3+1] + L[i*3+2]*L[k2*3+2];
        }
    }
}

// ---------------- kernel 1b: convert+transpose weights to fp16 [N][K] ----------------
__global__ void convw_kernel(const float* __restrict__ ew1, const float* __restrict__ ew2,
                             const float* __restrict__ nw1, const float* __restrict__ nw2)
{
    int idx = blockIdx.x * 256 + threadIdx.x;
    if (idx < DD*272) {
        int n = idx / 272, k = idx % 272;
        g_ew1T[idx] = (k < 268) ? __float2half(ew1[k*DD + n]) : __half(0.f);
    } else if (idx < DD*272 + DD*DD) {
        int j = idx - DD*272;
        int n = j / DD, k = j % DD;
        g_ew2T[j] = __float2half(ew2[k*DD + n]);
    } else if (idx < DD*272 + DD*DD + DD*256) {
        int j = idx - DD*272 - DD*DD;
        int n = j / 256, k = j % 256;
        g_nw1T[j] = __float2half(nw1[k*DD + n]);
    } else if (idx < DD*272 + 2*DD*DD + DD*256) {
        int j = idx - DD*272 - DD*DD - DD*256;
        int n = j / DD, k = j % DD;
        g_nw2T[j] = __float2half(nw2[k*DD + n]);
    }
}

// ---------------- kernel 2: zero scatter buffers ----------------
__global__ void zero_kernel()
{
    int idx = blockIdx.x * blockDim.x + threadIdx.x;
    if (idx < NN*DD) g_agg[idx] = 0.f;
    if (idx < NN)    g_cnt[idx] = 0;
}

// ---------------- kernel 3: cross-attention (tf32 mma), writes g_h16 ----------------
#define AT 64
#define SAH 132

__global__ __launch_bounds__(256, 2)
void attn_kernel(const float* __restrict__ nfeat, const float* __restrict__ frac,
                 const int* __restrict__ n2g,
                 const float* __restrict__ wq, const float* __restrict__ bq,
                 const float* __restrict__ wo, const float* __restrict__ bo,
                 const float* __restrict__ sw1, const float* __restrict__ sb1,
                 const float* __restrict__ sw2, const float* __restrict__ sb2)
{
    extern __shared__ float sm[];
    float* s_h   = sm;
    float* s_q   = s_h + AT*SAH;
    float* s_bb  = s_q + AT*SAH;
    float* s_sw1 = s_bb + 2*BBF;
    float* s_sw2 = s_sw1 + 3072;
    float* s_sb1 = s_sw2 + 1024;
    float* s_sb2 = s_sb1 + 128;
    float* s_enc = s_sb2 + 8;
    float* s_att = s_enc + AT*24;
    __shared__ int s_g[AT];

    int tid = threadIdx.x, lane = tid & 31, wid = tid >> 5;
    int wm = wid >> 2, wn = wid & 3;
    int n0 = blockIdx.x * AT;
    int brow = tid >> 5, bc4 = (tid & 31) * 4;

    if (tid < AT) s_g[tid] = n2g[min(n0 + tid, NN - 1)];

    #pragma unroll
    for (int it = 0; it < 8; it++) {
        int idx = tid + it*256;
        int r = idx >> 5, c4 = (idx & 31) * 4;
        int n = min(n0 + r, NN - 1);
        cpa16(s_h + r*SAH + c4, nfeat + (size_t)n*DD + c4);
    }
    #pragma unroll
    for (int it = 0; it < 3; it++) {
        int idx = tid + it*256;
        cpa16(s_sw1 + idx*4, sw1 + idx*4);
    }
    cpa16(s_sw2 + tid*4, sw2 + tid*4);
    if (tid < 32) cpa16(s_sb1 + tid*4, sb1 + tid*4);
    if (tid < 2)  cpa16(s_sb2 + tid*4, sb2 + tid*4);
    cpa16(s_bb + brow*SB + bc4, wq + (size_t)brow*DD + bc4);
    cpa16(s_bb + (brow+8)*SB + bc4, wq + (size_t)(brow+8)*DD + bc4);
    CP_COMMIT;

    {
        int n = tid >> 2, sub = tid & 3;
        int nn = min(n0 + n, NN - 1);
        float f0 = frac[nn*3+0], f1 = frac[nn*3+1], f2 = frac[nn*3+2];
        #pragma unroll
        for (int k = sub; k < 24; k += 4) {
            int ii = k % 12, c = ii >> 2, j = ii & 3;
            float fv = (c == 0) ? f0 : ((c == 1) ? f1 : f2);
            float ph = fv * ((float)(1 << j) * 3.14159265358979323846f);
            s_enc[n*24 + k] = (k < 12) ? sinf(ph) : cosf(ph);
        }
    }
    CP_WAIT0;
    __syncthreads();

    float acc[2][4][4];
    #pragma unroll
    for (int mf = 0; mf < 2; mf++)
        #pragma unroll
        for (int nf = 0; nf < 4; nf++)
            #pragma unroll
            for (int u = 0; u < 4; u++) acc[mf][nf][u] = 0.f;

    for (int ct = 0; ct < 8; ct++) {
        const float* wsrc = (ct < 7) ? (wq + (size_t)(ct*16 + 16)*DD) : wo;
        float* dbuf = s_bb + ((ct+1)&1)*BBF;
        cpa16(dbuf + brow*SB + bc4, wsrc + (size_t)brow*DD + bc4);
        cpa16(dbuf + (brow+8)*SB + bc4, wsrc + (size_t)(brow+8)*DD + bc4);
        CP_COMMIT;
        const float* bB = s_bb + (ct & 1)*BBF;
        #pragma unroll
        for (int kk = 0; kk < 16; kk += 8) {
            int kg = ct*16 + kk;
            uint32_t afr[2][4];
            #pragma unroll
            for (int mf = 0; mf < 2; mf++) LOAD_AFRAG(afr[mf], s_h, SAH, wm*32 + mf*16, kg);
            uint32_t bfr[4][2];
            #pragma unroll
            for (int nf = 0; nf < 4; nf++) LOAD_BFRAG(bfr[nf], bB, kk, wn*32 + nf*8);
            #pragma unroll
            for (int mf = 0; mf < 2; mf++)
                #pragma unroll
                for (int nf = 0; nf < 4; nf++)
                    mma_tf32(acc[mf][nf], afr[mf], bfr[nf]);
        }
        CP_WAIT0;
        __syncthreads();
    }
    #pragma unroll
    for (int mf = 0; mf < 2; mf++) {
        int r0 = wm*32 + mf*16 + (lane >> 2);
        #pragma unroll
        for (int nf = 0; nf < 4; nf++) {
            int n = wn*32 + nf*8 + (lane & 3)*2;
            float b0 = bq[n], b1 = bq[n + 1];
            s_q[r0*SAH + n]           = acc[mf][nf][0] + b0;
            s_q[r0*SAH + n + 1]       = acc[mf][nf][1] + b1;
            s_q[(r0 + 8)*SAH + n]     = acc[mf][nf][2] + b0;
            s_q[(r0 + 8)*SAH + n + 1] = acc[mf][nf][3] + b1;
            #pragma unroll
            for (int u = 0; u < 4; u++) acc[mf][nf][u] = 0.f;
        }
    }
    __syncthreads();

    {
        int n = tid >> 2, sub = tid & 3;
        int gg = s_g[n];
        float b8[8];
        #pragma unroll
        for (int t = 0; t < 8; t++) b8[t] = 0.f;
        const float* en = s_enc + n*24;
        for (int cc = 0; cc < 32; cc++) {
            int c = cc*4 + sub;
            float hid = s_sb1[c];
            #pragma unroll
            for (int k = 0; k < 24; k++) hid = fmaf(en[k], s_sw1[k*DD + c], hid);
            hid = silu_f(hid);
            #pragma unroll
            for (int t = 0; t < 8; t++) b8[t] = fmaf(hid, s_sw2[c*8 + t], b8[t]);
        }
        #pragma unroll
        for (int t = 0; t < 8; t++) {
            b8[t] += __shfl_xor_sync(0xffffffffu, b8[t], 1, 4);
            b8[t] += __shfl_xor_sync(0xffffffffu, b8[t], 2, 4);
        }
        int t0 = sub*2, t1 = t0 + 1;
        const float* K0 = g_KV + (size_t)(gg*TT + t0)*DD;
        const float* K1 = K0 + DD;
        const float* qq = s_q + n*SAH;
        float sc0 = 0.f, sc1 = 0.f;
        #pragma unroll 8
        for (int k = 0; k < DD; k++) {
            float qv = qq[k];
            sc0 = fmaf(qv, K0[k], sc0);
            sc1 = fmaf(qv, K1[k], sc1);
        }
        float v0 = sc0 * 0.08838834764831845f + b8[t0] + s_sb2[t0];
        float v1 = sc1 * 0.08838834764831845f + b8[t1] + s_sb2[t1];
        float m = fmaxf(v0, v1);
        m = fmaxf(m, __shfl_xor_sync(0xffffffffu, m, 1, 4));
        m = fmaxf(m, __shfl_xor_sync(0xffffffffu, m, 2, 4));
        float e0 = __expf(v0 - m), e1 = __expf(v1 - m);
        float s = e0 + e1;
        s += __shfl_xor_sync(0xffffffffu, s, 1, 4);
        s += __shfl_xor_sync(0xffffffffu, s, 2, 4);
        float inv = __fdividef(1.f, s);
        s_att[n*8 + t0] = e0 * inv;
        s_att[n*8 + t1] = e1 * inv;
    }
    __syncthreads();

    #pragma unroll
    for (int it = 0; it < 32; it++) {
        int idx = tid + it*256;
        int n = idx >> 7, c = idx & 127;
        const float* Vr = g_KV + KV_OFF + (size_t)s_g[n]*TT*DD + c;
        const float* at = s_att + n*8;
        float a = 0.f;
        #pragma unroll
        for (int t = 0; t < 8; t++) a = fmaf(at[t], Vr[t*DD], a);
        s_q[n*SAH + c] = a;
    }
    __syncthreads();

    for (int c = 0; c < 8; c++) {
        if (c < 7) {
            float* dbuf = s_bb + ((c+1)&1)*BBF;
            cpa16(dbuf + brow*SB + bc4, wo + (size_t)(c*16 + 16 + brow)*DD + bc4);
            cpa16(dbuf + (brow+8)*SB + bc4, wo + (size_t)(c*16 + 24 + brow)*DD + bc4);
            CP_COMMIT;
        }
        const float* bB = s_bb + (c & 1)*BBF;
        #pragma unroll
        for (int kk = 0; kk < 16; kk += 8) {
            int kg = c*16 + kk;
            uint32_t afr[2][4];
            #pragma unroll
            for (int mf = 0; mf < 2; mf++) LOAD_AFRAG(afr[mf], s_q, SAH, wm*32 + mf*16, kg);
            uint32_t bfr[4][2];
            #pragma unroll
            for (int nf = 0; nf < 4; nf++) LOAD_BFRAG(bfr[nf], bB, kk, wn*32 + nf*8);
            #pragma unroll
            for (int mf = 0; mf < 2; mf++)
                #pragma unroll
                for (int nf = 0; nf < 4; nf++)
                    mma_tf32(acc[mf][nf], afr[mf], bfr[nf]);
        }
        if (c < 7) { CP_WAIT0; }
        __syncthreads();
    }

    // epilogue: g_h16 = half(h + ca@wo + bo)
    #pragma unroll
    for (int mf = 0; mf < 2; mf++) {
        #pragma unroll
        for (int rr = 0; rr < 2; rr++) {
            int m = wm*32 + mf*16 + (lane >> 2) + rr*8;
            int n = n0 + m;
            if (n < NN) {
                __half* orow = g_h16 + (size_t)n*DD;
                const float* hrow = s_h + m*SAH;
                #pragma unroll
                for (int nf = 0; nf < 4; nf++) {
                    int col = wn*32 + nf*8 + (lane & 3)*2;
                    float v0 = hrow[col]     + acc[mf][nf][rr*2 + 0] + bo[col];
                    float v1 = hrow[col + 1] + acc[mf][nf][rr*2 + 1] + bo[col + 1];
                    *(__half2*)(orow + col) = __floats2half2_rn(v0, v1);
                }
            }
        }
    }
}

// ---------------- kernel 4: edge MLP, fp16 m16n8k16 ----------------
// Tile 128 edges x 128 outs, 8 warps (2 wm x 4 wn), warp tile 64x32 (mf=4, nf=4).
#define TM 128
#define SAh 280    // A stride halfs; bank step 12 -> conflict-free
#define SBh 24     // B stride halfs (16 k + 8 pad); bank step 12 -> conflict-free
#define BHB (128*SBh)

__global__ __launch_bounds__(256, 2)
void edge_kernel(const float* __restrict__ frac,
                 const int* __restrict__ edges, const int* __restrict__ e2g,
                 const float* __restrict__ eb1, const float* __restrict__ eb2)
{
    extern __shared__ __half smh[];
    __half* s_a  = smh;               // TM*SAh halfs
    __half* s_bb = smh + TM*SAh;      // 2*BHB halfs
    __shared__ int s_i[TM], s_j[TM];

    int tid  = threadIdx.x, lane = tid & 31, wid = tid >> 5;
    int wm = wid >> 2, wn = wid & 3;
    int e0 = blockIdx.x * TM;
    int bn = tid >> 1, bs = (tid & 1) * 8;   // B coop-load: row n, seg

    if (tid < TM) {
        s_i[tid] = edges[e0 + tid];
        s_j[tid] = edges[EE + e0 + tid];
    }
    if (tid >= 128 && tid < 256) {
        // nothing
    }
    __syncthreads();

    // async gather A rows (fp16, 16B = 8 halfs per seg; 128 edges x 2 rows x 16 segs)
    #pragma unroll
    for (int it = 0; it < 16; it++) {
        int idx = tid + it*256;
        int r = idx >> 4, seg = idx & 15;
        int e = r >> 1, p = r & 1;
        int node = p ? s_j[e] : s_i[e];
        cpa16(s_a + e*SAh + p*DD + seg*8, g_h16 + (size_t)node*DD + seg*8);
    }
    // ew1T chunk 0 -> buf0
    cpa16(s_bb + bn*SBh + bs, g_ew1T + bn*272 + bs);
    CP_COMMIT;

    // tail cols 256..279 (lip, fd, pad) + counts
    if (tid < TM) {
        int e = tid;
        const float* lp = g_lip + e2g[e0 + e]*9;
        #pragma unroll
        for (int u = 0; u < 9; u++) s_a[e*SAh + 256 + u] = __float2half(lp[u]);
        int ii = s_i[e], jj = s_j[e];
        #pragma unroll
        for (int c = 0; c < 3; c++) {
            float dd = frac[jj*3 + c] - frac[ii*3 + c];
            dd -= floorf(dd);
            s_a[e*SAh + 265 + c] = __float2half(dd);
        }
        #pragma unroll
        for (int u = 268; u < 280; u++) s_a[e*SAh + u] = __half(0.f);
        atomicAdd(&g_cnt[ii], 1);
    }

    float acc[4][4][4];
    #pragma unroll
    for (int mf = 0; mf < 4; mf++)
        #pragma unroll
        for (int nf = 0; nf < 4; nf++)
            #pragma unroll
            for (int u = 0; u < 4; u++) acc[mf][nf][u] = 0.f;

    CP_WAIT0;
    __syncthreads();

    // ---- GEMM1: K=272, 17 chunks of K=16 ----
    for (int ct = 0; ct < 17; ct++) {
        __half* dbuf = s_bb + ((ct+1)&1)*BHB;
        if (ct < 16) cpa16(dbuf + bn*SBh + bs, g_ew1T + bn*272 + (ct*16 + 16) + bs);
        else         cpa16(dbuf + bn*SBh + bs, g_ew2T + bn*128 + bs);
        CP_COMMIT;
        const __half* bB = s_bb + (ct & 1)*BHB;
        int kg = ct*16;
        uint32_t afr[4][4];
        #pragma unroll
        for (int mf = 0; mf < 4; mf++) LDA16(afr[mf], s_a, SAh, wm*64 + mf*16, kg);
        uint32_t bfr[4][2];
        #pragma unroll
        for (int nf = 0; nf < 4; nf++) LDB16(bfr[nf], bB, SBh, wn*32 + nf*8);
        #pragma unroll
        for (int mf = 0; mf < 4; mf++)
            #pragma unroll
            for (int nf = 0; nf < 4; nf++)
                mma_f16(acc[mf][nf], afr[mf], bfr[nf]);
        CP_WAIT0;
        __syncthreads();
    }

    // hidden = silu(acc + eb1) -> s_a cols 0..127 (half2 stores)
    #pragma unroll
    for (int mf = 0; mf < 4; mf++) {
        int r0 = wm*64 + mf*16 + (lane >> 2);
        #pragma unroll
        for (int nf = 0; nf < 4; nf++) {
            int n = wn*32 + nf*8 + (lane & 3)*2;
            float b0 = eb1[n], b1 = eb1[n + 1];
            *(__half2*)(s_a + r0*SAh + n) =
                __floats2half2_rn(silu_f(acc[mf][nf][0] + b0), silu_f(acc[mf][nf][1] + b1));
            *(__half2*)(s_a + (r0 + 8)*SAh + n) =
                __floats2half2_rn(silu_f(acc[mf][nf][2] + b0), silu_f(acc[mf][nf][3] + b1));
            #pragma unroll
            for (int u = 0; u < 4; u++) acc[mf][nf][u] = 0.f;
        }
    }
    __syncthreads();

    // ---- GEMM2: K=128, 8 chunks; chunk c in buf[(1+c)&1] ----
    for (int c = 0; c < 8; c++) {
        if (c < 7) {
            cpa16(s_bb + (c & 1)*BHB + bn*SBh + bs, g_ew2T + bn*128 + (c*16 + 16) + bs);
            CP_COMMIT;
        }
        const __half* bB = s_bb + ((1 + c) & 1)*BHB;
        int kg = c*16;
        uint32_t afr[4][4];
        #pragma unroll
        for (int mf = 0; mf < 4; mf++) LDA16(afr[mf], s_a, SAh, wm*64 + mf*16, kg);
        uint32_t bfr[4][2];
        #pragma unroll
        for (int nf = 0; nf < 4; nf++) LDB16(bfr[nf], bB, SBh, wn*32 + nf*8);
        #pragma unroll
        for (int mf = 0; mf < 4; mf++)
            #pragma unroll
            for (int nf = 0; nf < 4; nf++)
                mma_f16(acc[mf][nf], afr[mf], bfr[nf]);
        if (c < 7) { CP_WAIT0; }
        __syncthreads();
    }

    // epilogue: silu + bias, red.v2 scatter into g_agg (fp32)
    #pragma unroll
    for (int mf = 0; mf < 4; mf++) {
        #pragma unroll
        for (int rr = 0; rr < 2; rr++) {
            int m = wm*64 + mf*16 + (lane >> 2) + rr*8;
            float* ap = g_agg + (size_t)s_i[m]*DD;
            #pragma unroll
            for (int nf = 0; nf < 4; nf++) {
                int n = wn*32 + nf*8 + (lane & 3)*2;
                float v0 = silu_f(acc[mf][nf][rr*2 + 0] + eb2[n]);
                float v1 = silu_f(acc[mf][nf][rr*2 + 1] + eb2[n + 1]);
                asm volatile("red.global.add.v2.f32 [%0], {%1, %2};"
                             :: "l"(ap + n), "f"(v0), "f"(v1) : "memory");
            }
        }
    }
}

// ---------------- kernel 5: node MLP, fp16 m16n8k16 ----------------
#define TN 128
#define SAn 264    // bank step 4 -> conflict-free

__global__ __launch_bounds__(256, 2)
void node_kernel(const float* __restrict__ nfeat,
                 const float* __restrict__ nb1, const float* __restrict__ nb2,
                 float* __restrict__ out)
{
    extern __shared__ __half smh[];
    __half* s_a  = smh;               // TN*SAn
    __half* s_bb = smh + TN*SAn;      // 2*BHB
    __shared__ float s_cnt[TN];

    int tid  = threadIdx.x, lane = tid & 31, wid = tid >> 5;
    int wm = wid >> 2, wn = wid & 3;
    int n0 = blockIdx.x * TN;
    int bn = tid >> 1, bs = (tid & 1) * 8;

    if (tid < TN) {
        int n = min(n0 + tid, NN - 1);
        s_cnt[tid] = fmaxf((float)g_cnt[n], 1.f);
    }
    // h rows (fp16 direct)
    #pragma unroll
    for (int it = 0; it < 8; it++) {
        int idx = tid + it*256;
        int r = idx >> 4, seg = idx & 15;
        int n = min(n0 + r, NN - 1);
        cpa16(s_a + r*SAn + seg*8, g_h16 + (size_t)n*DD + seg*8);
    }
    cpa16(s_bb + bn*SBh + bs, g_nw1T + bn*256 + bs);
    CP_COMMIT;
    __syncthreads();   // s_cnt visible

    // agg/cnt -> cols 128..255 (fp32 load, convert)
    #pragma unroll
    for (int it = 0; it < 16; it++) {
        int idx = tid + it*256;
        int r = idx >> 5, c4 = (idx & 31) * 4;
        int n = min(n0 + r, NN - 1);
        float inv = __fdividef(1.f, s_cnt[r]);
        float4 v = *(const float4*)(g_agg + (size_t)n*DD + c4);
        __half* dst = s_a + r*SAn + DD + c4;
        *(__half2*)(dst)     = __floats2half2_rn(v.x * inv, v.y * inv);
        *(__half2*)(dst + 2) = __floats2half2_rn(v.z * inv, v.w * inv);
    }

    float acc[4][4][4];
    #pragma unroll
    for (int mf = 0; mf < 4; mf++)
        #pragma unroll
        for (int nf = 0; nf < 4; nf++)
            #pragma unroll
            for (int u = 0; u < 4; u++) acc[mf][nf][u] = 0.f;

    CP_WAIT0;
    __syncthreads();

    // ---- GEMM1: K=256, 16 chunks ----
    for (int ct = 0; ct < 16; ct++) {
        __half* dbuf = s_bb + ((ct+1)&1)*BHB;
        if (ct < 15) cpa16(dbuf + bn*SBh + bs, g_nw1T + bn*256 + (ct*16 + 16) + bs);
        else         cpa16(dbuf + bn*SBh + bs, g_nw2T + bn*128 + bs);
        CP_COMMIT;
        const __half* bB = s_bb + (ct & 1)*BHB;
        int kg = ct*16;
        uint32_t afr[4][4];
        #pragma unroll
        for (int mf = 0; mf < 4; mf++) LDA16(afr[mf], s_a, SAn, wm*64 + mf*16, kg);
        uint32_t bfr[4][2];
        #pragma unroll
        for (int nf = 0; nf < 4; nf++) LDB16(bfr[nf], bB, SBh, wn*32 + nf*8);
        #pragma unroll
        for (int mf = 0; mf < 4; mf++)
            #pragma unroll
            for (int nf = 0; nf < 4; nf++)
                mma_f16(acc[mf][nf], afr[mf], bfr[nf]);
        CP_WAIT0;
        __syncthreads();
    }

    // hidden -> s_a cols 0..127
    #pragma unroll
    for (int mf = 0; mf < 4; mf++) {
        int r0 = wm*64 + mf*16 + (lane >> 2);
        #pragma unroll
        for (int nf = 0; nf < 4; nf++) {
            int n = wn*32 + nf*8 + (lane & 3)*2;
            float b0 = nb1[n], b1 = nb1[n + 1];
            *(__half2*)(s_a + r0*SAn + n) =
                __floats2half2_rn(silu_f(acc[mf][nf][0] + b0), silu_f(acc[mf][nf][1] + b1));
            *(__half2*)(s_a + (r0 + 8)*SAn + n) =
                __floats2half2_rn(silu_f(acc[mf][nf][2] + b0), silu_f(acc[mf][nf][3] + b1));
            #pragma unroll
            for (int u = 0; u < 4; u++) acc[mf][nf][u] = 0.f;
        }
    }
    __syncthreads();

    // ---- GEMM2: K=128, 8 chunks; chunk c in buf[c&1] ----
    for (int c = 0; c < 8; c++) {
        if (c < 7) {
            cpa16(s_bb + ((c+1)&1)*BHB + bn*SBh + bs, g_nw2T + bn*128 + (c*16 + 16) + bs);
            CP_COMMIT;
        }
        const __half* bB = s_bb + (c & 1)*BHB;
        int kg = c*16;
        uint32_t afr[4][4];
        #pragma unroll
        for (int mf = 0; mf < 4; mf++) LDA16(afr[mf], s_a, SAn, wm*64 + mf*16, kg);
        uint32_t bfr[4][2];
        #pragma unroll
        for (int nf = 0; nf < 4; nf++) LDB16(bfr[nf], bB, SBh, wn*32 + nf*8);
        #pragma unroll
        for (int mf = 0; mf < 4; mf++)
            #pragma unroll
            for (int nf = 0; nf < 4; nf++)
                mma_f16(acc[mf][nf], afr[mf], bfr[nf]);
        if (c < 7) { CP_WAIT0; }
        __syncthreads();
    }

    // epilogue: out = nfeat + silu(acc + nb2)
    #pragma unroll
    for (int mf = 0; mf < 4; mf++) {
        #pragma unroll
        for (int rr = 0; rr < 2; rr++) {
            int m = wm*64 + mf*16 + (lane >> 2) + rr*8;
            int n = n0 + m;
            if (n < NN) {
                const float* nfr = nfeat + (size_t)n*DD;
                float* orow = out + (size_t)n*DD;
                #pragma unroll
                for (int nf = 0; nf < 4; nf++) {
                    int col = wn*32 + nf*8 + (lane & 3)*2;
                    orow[col]     = nfr[col]     + silu_f(acc[mf][nf][rr*2 + 0] + nb2[col]);
                    orow[col + 1] = nfr[col + 1] + silu_f(acc[mf][nf][rr*2 + 1] + nb2[col + 1]);
                }
            }
        }
    }
}

// ---------------- launch ----------------
extern "C" void kernel_launch(void* const* d_in, const int* in_sizes, int n_in,
                              void* d_out, int out_size)
{
    const float* node_features = (const float*)d_in[0];
    const float* cond = (const float*)d_in[1];
    const int*   n2g  = (const int*)d_in[2];
    const float* frac = (const float*)d_in[3];
    const float* lat  = (const float*)d_in[4];
    const int*   edges= (const int*)d_in[5];
    const int*   e2g  = (const int*)d_in[6];
    const float* wq = (const float*)d_in[7];
    const float* bq = (const float*)d_in[8];
    const float* wk = (const float*)d_in[9];
    const float* bk = (const float*)d_in[10];
    const float* wv = (const float*)d_in[11];
    const float* bv = (const float*)d_in[12];
    const float* wo = (const float*)d_in[13];
    const float* bo = (const float*)d_in[14];
    const float* sw1= (const float*)d_in[15];
    const float* sb1= (const float*)d_in[16];
    const float* sw2= (const float*)d_in[17];
    const float* sb2= (const float*)d_in[18];
    const float* ew1= (const float*)d_in[19];
    const float* eb1= (const float*)d_in[20];
    const float* ew2= (const float*)d_in[21];
    const float* eb2= (const float*)d_in[22];
    const float* nw1= (const float*)d_in[23];
    const float* nb1= (const float*)d_in[24];
    const float* nw2= (const float*)d_in[25];
    const float* nb2= (const float*)d_in[26];
    float* out = (float*)d_out;

    const int attn_smem = (2*AT*SAH + 2*BBF + 3072 + 1024 + 128 + 8 + AT*24 + AT*8) * 4;
    const int edge_smem = (TM*SAh + 2*BHB) * 2;   // halfs
    const int node_smem = (TN*SAn + 2*BHB) * 2;
    cudaFuncSetAttribute(attn_kernel, cudaFuncAttributeMaxDynamicSharedMemorySize, attn_smem);
    cudaFuncSetAttribute(edge_kernel, cudaFuncAttributeMaxDynamicSharedMemorySize, edge_smem);
    cudaFuncSetAttribute(node_kernel, cudaFuncAttributeMaxDynamicSharedMemorySize, node_smem);

    prep_kernel<<<BB*TT + BB, 128>>>(cond, wk, bk, wv, bv, lat);
    convw_kernel<<<(DD*272 + 2*DD*DD + DD*256 + 255)/256, 256>>>(ew1, ew2, nw1, nw2);
    zero_kernel<<<(NN*DD + 255) / 256, 256>>>();
    attn_kernel<<<(NN + AT - 1) / AT, 256, attn_smem>>>(node_features, frac, n2g,
                                                        wq, bq, wo, bo, sw1, sb1, sw2, sb2);
    edge_kernel<<<EE / TM, 256, edge_smem>>>(frac, edges, e2g, eb1, eb2);
    node_kernel<<<(NN + TN - 1) / TN, 256, node_smem>>>(node_features, nb1, nb2, out);
}

// round 7
// speedup vs baseline: 2.3104x; 1.0022x over previous
#include <cuda_runtime.h>
#include <cuda_fp16.h>
#include <math.h>
#include <stdint.h>

#define NN 50000
#define EE 800000
#define BB 256
#define DD 128
#define TT 8
#define KV_OFF (BB*TT*DD)

// ---------------- scratch (no allocations allowed) ----------------
__device__ __half g_h16[(size_t)NN*DD];     // post-attention node states (fp16)
__device__ float  g_KV[2*BB*TT*DD];         // Kc then Vc (fp32)
__device__ float  g_lip[BB*9];              // lattice inner products
__device__ float  g_agg[(size_t)NN*DD];     // scatter sums (fp32 atomics)
__device__ int    g_cnt[NN];                // scatter counts
// pre-converted, pre-transposed fp16 weights [N][K]
__device__ __half g_ew1T[DD*272];
__device__ __half g_ew2T[DD*DD];
__device__ __half g_nw1T[DD*256];
__device__ __half g_nw2T[DD*DD];

__device__ __forceinline__ float silu_f(float x) {
    return __fdividef(x, 1.f + __expf(-x));
}

// tf32 mma (attention kernel only)
__device__ __forceinline__ void mma_tf32(float* c, const uint32_t* a, const uint32_t* b) {
    asm volatile(
        "mma.sync.aligned.m16n8k8.row.col.f32.tf32.tf32.f32 "
        "{%0,%1,%2,%3}, {%4,%5,%6,%7}, {%8,%9}, {%0,%1,%2,%3};\n"
        : "+f"(c[0]), "+f"(c[1]), "+f"(c[2]), "+f"(c[3])
        : "r"(a[0]), "r"(a[1]), "r"(a[2]), "r"(a[3]), "r"(b[0]), "r"(b[1]));
}
// fp16 mma, fp32 accumulate
__device__ __forceinline__ void mma_f16(float* c, const uint32_t* a, const uint32_t* b) {
    asm volatile(
        "mma.sync.aligned.m16n8k16.row.col.f32.f16.f16.f32 "
        "{%0,%1,%2,%3}, {%4,%5,%6,%7}, {%8,%9}, {%0,%1,%2,%3};\n"
        : "+f"(c[0]), "+f"(c[1]), "+f"(c[2]), "+f"(c[3])
        : "r"(a[0]), "r"(a[1]), "r"(a[2]), "r"(a[3]), "r"(b[0]), "r"(b[1]));
}

__device__ __forceinline__ void cpa16(void* dst, const void* src) {
    uint32_t d = (uint32_t)__cvta_generic_to_shared(dst);
    asm volatile("cp.async.cg.shared.global [%0], [%1], 16;" :: "r"(d), "l"(src));
}
#define CP_COMMIT asm volatile("cp.async.commit_group;" ::: "memory")
#define CP_WAIT0  asm volatile("cp.async.wait_group 0;" ::: "memory")

// -------- fp16 fragment loads (A row-major [m][k], B as [n][k]) --------
#define LDA16(afr, base, SAx, rowbase, kg)                                        \
    {                                                                             \
        const __half* ap_ = (base) + ((rowbase) + (lane >> 2))*(SAx) + (kg) + ((lane & 3)*2); \
        afr[0] = *(const uint32_t*)(ap_);                                         \
        afr[1] = *(const uint32_t*)(ap_ + 8*(SAx));                               \
        afr[2] = *(const uint32_t*)(ap_ + 8);                                     \
        afr[3] = *(const uint32_t*)(ap_ + 8*(SAx) + 8);                           \
    }
#define LDB16(bfr, bB, SBx, ncol)                                                 \
    {                                                                             \
        const __half* bp_ = (bB) + ((ncol) + (lane >> 2))*(SBx) + ((lane & 3)*2); \
        bfr[0] = *(const uint32_t*)(bp_);                                         \
        bfr[1] = *(const uint32_t*)(bp_ + 8);                                     \
    }

// tf32 frag loads (attn)
#define SB 136
#define BBF (16*SB)
#define LOAD_AFRAG(afr, s_a, SAx, rowbase, kg)                                   \
    {                                                                            \
        const float* ap_ = (s_a) + ((rowbase) + (lane >> 2))*(SAx) + (kg) + (lane & 3); \
        afr[0] = __float_as_uint(ap_[0]);                                        \
        afr[1] = __float_as_uint(ap_[8*(SAx)]);                                  \
        afr[2] = __float_as_uint(ap_[4]);                                        \
        afr[3] = __float_as_uint(ap_[8*(SAx) + 4]);                              \
    }
#define LOAD_BFRAG(bfr, bB, kk, ncol)                                            \
    {                                                                            \
        const float* bp_ = (bB) + ((kk) + (lane & 3))*SB + (ncol) + (lane >> 2); \
        bfr[0] = __float_as_uint(bp_[0]);                                        \
        bfr[1] = __float_as_uint(bp_[4*SB]);                                     \
    }

// ---------------- kernel 1: K/V projection + lattice gram ----------------
__global__ void prep_kernel(const float* __restrict__ cond,
                            const float* __restrict__ wk, const float* __restrict__ bk,
                            const float* __restrict__ wv, const float* __restrict__ bv,
                            const float* __restrict__ lat)
{
    int b = blockIdx.x;
    if (b < BB*TT) {
        __shared__ float s_c[DD];
        int d = threadIdx.x;
        s_c[d] = cond[b*DD + d];
        __syncthreads();
        float ka = bk[d], va = bv[d];
        #pragma unroll 8
        for (int k = 0; k < DD; k++) {
            float c = s_c[k];
            ka = fmaf(c, wk[k*DD + d], ka);
            va = fmaf(c, wv[k*DD + d], va);
        }
        g_KV[b*DD + d] = ka;
        g_KV[KV_OFF + b*DD + d] = va;
    } else {
        int bb = b - BB*TT;
        int t = threadIdx.x;
        if (t < 9) {
            int i = t / 3, k2 = t % 3;
            const float* L = lat + bb*9;
            g_lip[bb*9 + t] = L[i*3+0]*L[k2*3+0] + L[i*3+1]*L[k2*3+1] + L[i*3+2]*L[k2*3+2];
        }
    }
}

// ---------------- kernel 1b: convert+transpose weights to fp16 [N][K] ----------------
__global__ void convw_kernel(const float* __restrict__ ew1, const float* __restrict__ ew2,
                             const float* __restrict__ nw1, const float* __restrict__ nw2)
{
    int idx = blockIdx.x * 256 + threadIdx.x;
    if (idx < DD*272) {
        int n = idx / 272, k = idx % 272;
        g_ew1T[idx] = (k < 268) ? __float2half(ew1[k*DD + n]) : __half(0.f);
    } else if (idx < DD*272 + DD*DD) {
        int j = idx - DD*272;
        int n = j / DD, k = j % DD;
        g_ew2T[j] = __float2half(ew2[k*DD + n]);
    } else if (idx < DD*272 + DD*DD + DD*256) {
        int j = idx - DD*272 - DD*DD;
        int n = j / 256, k = j % 256;
        g_nw1T[j] = __float2half(nw1[k*DD + n]);
    } else if (idx < DD*272 + 2*DD*DD + DD*256) {
        int j = idx - DD*272 - DD*DD - DD*256;
        int n = j / DD, k = j % DD;
        g_nw2T[j] = __float2half(nw2[k*DD + n]);
    }
}

// ---------------- kernel 2: zero scatter buffers ----------------
__global__ void zero_kernel()
{
    int idx = blockIdx.x * blockDim.x + threadIdx.x;
    if (idx < NN*DD) g_agg[idx] = 0.f;
    if (idx < NN)    g_cnt[idx] = 0;
}

// ---------------- kernel 3: cross-attention (tf32 mma), writes g_h16 ----------------
#define AT 64
#define SAH 132

__global__ __launch_bounds__(256, 2)
void attn_kernel(const float* __restrict__ nfeat, const float* __restrict__ frac,
                 const int* __restrict__ n2g,
                 const float* __restrict__ wq, const float* __restrict__ bq,
                 const float* __restrict__ wo, const float* __restrict__ bo,
                 const float* __restrict__ sw1, const float* __restrict__ sb1,
                 const float* __restrict__ sw2, const float* __restrict__ sb2)
{
    extern __shared__ float sm[];
    float* s_h   = sm;
    float* s_q   = s_h + AT*SAH;
    float* s_bb  = s_q + AT*SAH;
    float* s_sw1 = s_bb + 2*BBF;
    float* s_sw2 = s_sw1 + 3072;
    float* s_sb1 = s_sw2 + 1024;
    float* s_sb2 = s_sb1 + 128;
    float* s_enc = s_sb2 + 8;
    float* s_att = s_enc + AT*24;
    __shared__ int s_g[AT];

    int tid = threadIdx.x, lane = tid & 31, wid = tid >> 5;
    int wm = wid >> 2, wn = wid & 3;
    int n0 = blockIdx.x * AT;
    int brow = tid >> 5, bc4 = (tid & 31) * 4;

    if (tid < AT) s_g[tid] = n2g[min(n0 + tid, NN - 1)];

    #pragma unroll
    for (int it = 0; it < 8; it++) {
        int idx = tid + it*256;
        int r = idx >> 5, c4 = (idx & 31) * 4;
        int n = min(n0 + r, NN - 1);
        cpa16(s_h + r*SAH + c4, nfeat + (size_t)n*DD + c4);
    }
    #pragma unroll
    for (int it = 0; it < 3; it++) {
        int idx = tid + it*256;
        cpa16(s_sw1 + idx*4, sw1 + idx*4);
    }
    cpa16(s_sw2 + tid*4, sw2 + tid*4);
    if (tid < 32) cpa16(s_sb1 + tid*4, sb1 + tid*4);
    if (tid < 2)  cpa16(s_sb2 + tid*4, sb2 + tid*4);
    cpa16(s_bb + brow*SB + bc4, wq + (size_t)brow*DD + bc4);
    cpa16(s_bb + (brow+8)*SB + bc4, wq + (size_t)(brow+8)*DD + bc4);
    CP_COMMIT;

    {
        int n = tid >> 2, sub = tid & 3;
        int nn = min(n0 + n, NN - 1);
        float f0 = frac[nn*3+0], f1 = frac[nn*3+1], f2 = frac[nn*3+2];
        #pragma unroll
        for (int k = sub; k < 24; k += 4) {
            int ii = k % 12, c = ii >> 2, j = ii & 3;
            float fv = (c == 0) ? f0 : ((c == 1) ? f1 : f2);
            float ph = fv * ((float)(1 << j) * 3.14159265358979323846f);
            s_enc[n*24 + k] = (k < 12) ? sinf(ph) : cosf(ph);
        }
    }
    CP_WAIT0;
    __syncthreads();

    float acc[2][4][4];
    #pragma unroll
    for (int mf = 0; mf < 2; mf++)
        #pragma unroll
        for (int nf = 0; nf < 4; nf++)
            #pragma unroll
            for (int u = 0; u < 4; u++) acc[mf][nf][u] = 0.f;

    for (int ct = 0; ct < 8; ct++) {
        const float* wsrc = (ct < 7) ? (wq + (size_t)(ct*16 + 16)*DD) : wo;
        float* dbuf = s_bb + ((ct+1)&1)*BBF;
        cpa16(dbuf + brow*SB + bc4, wsrc + (size_t)brow*DD + bc4);
        cpa16(dbuf + (brow+8)*SB + bc4, wsrc + (size_t)(brow+8)*DD + bc4);
        CP_COMMIT;
        const float* bB = s_bb + (ct & 1)*BBF;
        #pragma unroll
        for (int kk = 0; kk < 16; kk += 8) {
            int kg = ct*16 + kk;
            uint32_t afr[2][4];
            #pragma unroll
            for (int mf = 0; mf < 2; mf++) LOAD_AFRAG(afr[mf], s_h, SAH, wm*32 + mf*16, kg);
            uint32_t bfr[4][2];
            #pragma unroll
            for (int nf = 0; nf < 4; nf++) LOAD_BFRAG(bfr[nf], bB, kk, wn*32 + nf*8);
            #pragma unroll
            for (int mf = 0; mf < 2; mf++)
                #pragma unroll
                for (int nf = 0; nf < 4; nf++)
                    mma_tf32(acc[mf][nf], afr[mf], bfr[nf]);
        }
        CP_WAIT0;
        __syncthreads();
    }
    #pragma unroll
    for (int mf = 0; mf < 2; mf++) {
        int r0 = wm*32 + mf*16 + (lane >> 2);
        #pragma unroll
        for (int nf = 0; nf < 4; nf++) {
            int n = wn*32 + nf*8 + (lane & 3)*2;
            float b0 = bq[n], b1 = bq[n + 1];
            s_q[r0*SAH + n]           = acc[mf][nf][0] + b0;
            s_q[r0*SAH + n + 1]       = acc[mf][nf][1] + b1;
            s_q[(r0 + 8)*SAH + n]     = acc[mf][nf][2] + b0;
            s_q[(r0 + 8)*SAH + n + 1] = acc[mf][nf][3] + b1;
            #pragma unroll
            for (int u = 0; u < 4; u++) acc[mf][nf][u] = 0.f;
        }
    }
    __syncthreads();

    {
        int n = tid >> 2, sub = tid & 3;
        int gg = s_g[n];
        float b8[8];
        #pragma unroll
        for (int t = 0; t < 8; t++) b8[t] = 0.f;
        const float* en = s_enc + n*24;
        for (int cc = 0; cc < 32; cc++) {
            int c = cc*4 + sub;
            float hid = s_sb1[c];
            #pragma unroll
            for (int k = 0; k < 24; k++) hid = fmaf(en[k], s_sw1[k*DD + c], hid);
            hid = silu_f(hid);
            #pragma unroll
            for (int t = 0; t < 8; t++) b8[t] = fmaf(hid, s_sw2[c*8 + t], b8[t]);
        }
        #pragma unroll
        for (int t = 0; t < 8; t++) {
            b8[t] += __shfl_xor_sync(0xffffffffu, b8[t], 1, 4);
            b8[t] += __shfl_xor_sync(0xffffffffu, b8[t], 2, 4);
        }
        int t0 = sub*2, t1 = t0 + 1;
        const float* K0 = g_KV + (size_t)(gg*TT + t0)*DD;
        const float* K1 = K0 + DD;
        const float* qq = s_q + n*SAH;
        float sc0 = 0.f, sc1 = 0.f;
        #pragma unroll 8
        for (int k = 0; k < DD; k++) {
            float qv = qq[k];
            sc0 = fmaf(qv, K0[k], sc0);
            sc1 = fmaf(qv, K1[k], sc1);
        }
        float v0 = sc0 * 0.08838834764831845f + b8[t0] + s_sb2[t0];
        float v1 = sc1 * 0.08838834764831845f + b8[t1] + s_sb2[t1];
        float m = fmaxf(v0, v1);
        m = fmaxf(m, __shfl_xor_sync(0xffffffffu, m, 1, 4));
        m = fmaxf(m, __shfl_xor_sync(0xffffffffu, m, 2, 4));
        float e0 = __expf(v0 - m), e1 = __expf(v1 - m);
        float s = e0 + e1;
        s += __shfl_xor_sync(0xffffffffu, s, 1, 4);
        s += __shfl_xor_sync(0xffffffffu, s, 2, 4);
        float inv = __fdividef(1.f, s);
        s_att[n*8 + t0] = e0 * inv;
        s_att[n*8 + t1] = e1 * inv;
    }
    __syncthreads();

    #pragma unroll
    for (int it = 0; it < 32; it++) {
        int idx = tid + it*256;
        int n = idx >> 7, c = idx & 127;
        const float* Vr = g_KV + KV_OFF + (size_t)s_g[n]*TT*DD + c;
        const float* at = s_att + n*8;
        float a = 0.f;
        #pragma unroll
        for (int t = 0; t < 8; t++) a = fmaf(at[t], Vr[t*DD], a);
        s_q[n*SAH + c] = a;
    }
    __syncthreads();

    for (int c = 0; c < 8; c++) {
        if (c < 7) {
            float* dbuf = s_bb + ((c+1)&1)*BBF;
            cpa16(dbuf + brow*SB + bc4, wo + (size_t)(c*16 + 16 + brow)*DD + bc4);
            cpa16(dbuf + (brow+8)*SB + bc4, wo + (size_t)(c*16 + 24 + brow)*DD + bc4);
            CP_COMMIT;
        }
        const float* bB = s_bb + (c & 1)*BBF;
        #pragma unroll
        for (int kk = 0; kk < 16; kk += 8) {
            int kg = c*16 + kk;
            uint32_t afr[2][4];
            #pragma unroll
            for (int mf = 0; mf < 2; mf++) LOAD_AFRAG(afr[mf], s_q, SAH, wm*32 + mf*16, kg);
            uint32_t bfr[4][2];
            #pragma unroll
            for (int nf = 0; nf < 4; nf++) LOAD_BFRAG(bfr[nf], bB, kk, wn*32 + nf*8);
            #pragma unroll
            for (int mf = 0; mf < 2; mf++)
                #pragma unroll
                for (int nf = 0; nf < 4; nf++)
                    mma_tf32(acc[mf][nf], afr[mf], bfr[nf]);
        }
        if (c < 7) { CP_WAIT0; }
        __syncthreads();
    }

    // epilogue: g_h16 = half(h + ca@wo + bo)
    #pragma unroll
    for (int mf = 0; mf < 2; mf++) {
        #pragma unroll
        for (int rr = 0; rr < 2; rr++) {
            int m = wm*32 + mf*16 + (lane >> 2) + rr*8;
            int n = n0 + m;
            if (n < NN) {
                __half* orow = g_h16 + (size_t)n*DD;
                const float* hrow = s_h + m*SAH;
                #pragma unroll
                for (int nf = 0; nf < 4; nf++) {
                    int col = wn*32 + nf*8 + (lane & 3)*2;
                    float v0 = hrow[col]     + acc[mf][nf][rr*2 + 0] + bo[col];
                    float v1 = hrow[col + 1] + acc[mf][nf][rr*2 + 1] + bo[col + 1];
                    *(__half2*)(orow + col) = __floats2half2_rn(v0, v1);
                }
            }
        }
    }
}

// ---------------- kernel 4: edge MLP, fp16 m16n8k16 ----------------
// Tile 128 edges x 128 outs, 8 warps (2 wm x 4 wn), warp tile 64x32 (mf=4, nf=4).
#define TM 128
#define SAh 280    // A stride halfs; bank step 12 -> conflict-free
#define SBh 24     // B stride halfs (16 k + 8 pad); bank step 12 -> conflict-free
#define BHB (128*SBh)

__global__ __launch_bounds__(256, 2)
void edge_kernel(const float* __restrict__ frac,
                 const int* __restrict__ edges, const int* __restrict__ e2g,
                 const float* __restrict__ eb1, const float* __restrict__ eb2)
{
    extern __shared__ __half smh[];
    __half* s_a  = smh;               // TM*SAh halfs
    __half* s_bb = smh + TM*SAh;      // 2*BHB halfs
    __shared__ int s_i[TM], s_j[TM];

    int tid  = threadIdx.x, lane = tid & 31, wid = tid >> 5;
    int wm = wid >> 2, wn = wid & 3;
    int e0 = blockIdx.x * TM;
    int bn = tid >> 1, bs = (tid & 1) * 8;   // B coop-load: row n, seg

    if (tid < TM) {
        s_i[tid] = edges[e0 + tid];
        s_j[tid] = edges[EE + e0 + tid];
    }
    if (tid >= 128 && tid < 256) {
        // nothing
    }
    __syncthreads();

    // async gather A rows (fp16, 16B = 8 halfs per seg; 128 edges x 2 rows x 16 segs)
    #pragma unroll
    for (int it = 0; it < 16; it++) {
        int idx = tid + it*256;
        int r = idx >> 4, seg = idx & 15;
        int e = r >> 1, p = r & 1;
        int node = p ? s_j[e] : s_i[e];
        cpa16(s_a + e*SAh + p*DD + seg*8, g_h16 + (size_t)node*DD + seg*8);
    }
    // ew1T chunk 0 -> buf0
    cpa16(s_bb + bn*SBh + bs, g_ew1T + bn*272 + bs);
    CP_COMMIT;

    // tail cols 256..279 (lip, fd, pad) + counts
    if (tid < TM) {
        int e = tid;
        const float* lp = g_lip + e2g[e0 + e]*9;
        #pragma unroll
        for (int u = 0; u < 9; u++) s_a[e*SAh + 256 + u] = __float2half(lp[u]);
        int ii = s_i[e], jj = s_j[e];
        #pragma unroll
        for (int c = 0; c < 3; c++) {
            float dd = frac[jj*3 + c] - frac[ii*3 + c];
            dd -= floorf(dd);
            s_a[e*SAh + 265 + c] = __float2half(dd);
        }
        #pragma unroll
        for (int u = 268; u < 280; u++) s_a[e*SAh + u] = __half(0.f);
        atomicAdd(&g_cnt[ii], 1);
    }

    float acc[4][4][4];
    #pragma unroll
    for (int mf = 0; mf < 4; mf++)
        #pragma unroll
        for (int nf = 0; nf < 4; nf++)
            #pragma unroll
            for (int u = 0; u < 4; u++) acc[mf][nf][u] = 0.f;

    CP_WAIT0;
    __syncthreads();

    // ---- GEMM1: K=272, 17 chunks of K=16 ----
    for (int ct = 0; ct < 17; ct++) {
        __half* dbuf = s_bb + ((ct+1)&1)*BHB;
        if (ct < 16) cpa16(dbuf + bn*SBh + bs, g_ew1T + bn*272 + (ct*16 + 16) + bs);
        else         cpa16(dbuf + bn*SBh + bs, g_ew2T + bn*128 + bs);
        CP_COMMIT;
        const __half* bB = s_bb + (ct & 1)*BHB;
        int kg = ct*16;
        uint32_t afr[4][4];
        #pragma unroll
        for (int mf = 0; mf < 4; mf++) LDA16(afr[mf], s_a, SAh, wm*64 + mf*16, kg);
        uint32_t bfr[4][2];
        #pragma unroll
        for (int nf = 0; nf < 4; nf++) LDB16(bfr[nf], bB, SBh, wn*32 + nf*8);
        #pragma unroll
        for (int mf = 0; mf < 4; mf++)
            #pragma unroll
            for (int nf = 0; nf < 4; nf++)
                mma_f16(acc[mf][nf], afr[mf], bfr[nf]);
        CP_WAIT0;
        __syncthreads();
    }

    // hidden = silu(acc + eb1) -> s_a cols 0..127 (half2 stores)
    #pragma unroll
    for (int mf = 0; mf < 4; mf++) {
        int r0 = wm*64 + mf*16 + (lane >> 2);
        #pragma unroll
        for (int nf = 0; nf < 4; nf++) {
            int n = wn*32 + nf*8 + (lane & 3)*2;
            float b0 = eb1[n], b1 = eb1[n + 1];
            *(__half2*)(s_a + r0*SAh + n) =
                __floats2half2_rn(silu_f(acc[mf][nf][0] + b0), silu_f(acc[mf][nf][1] + b1));
            *(__half2*)(s_a + (r0 + 8)*SAh + n) =
                __floats2half2_rn(silu_f(acc[mf][nf][2] + b0), silu_f(acc[mf][nf][3] + b1));
            #pragma unroll
            for (int u = 0; u < 4; u++) acc[mf][nf][u] = 0.f;
        }
    }
    __syncthreads();

    // ---- GEMM2: K=128, 8 chunks; chunk c in buf[(1+c)&1] ----
    for (int c = 0; c < 8; c++) {
        if (c < 7) {
            cpa16(s_bb + (c & 1)*BHB + bn*SBh + bs, g_ew2T + bn*128 + (c*16 + 16) + bs);
            CP_COMMIT;
        }
        const __half* bB = s_bb + ((1 + c) & 1)*BHB;
        int kg = c*16;
        uint32_t afr[4][4];
        #pragma unroll
        for (int mf = 0; mf < 4; mf++) LDA16(afr[mf], s_a, SAh, wm*64 + mf*16, kg);
        uint32_t bfr[4][2];
        #pragma unroll
        for (int nf = 0; nf < 4; nf++) LDB16(bfr[nf], bB, SBh, wn*32 + nf*8);
        #pragma unroll
        for (int mf = 0; mf < 4; mf++)
            #pragma unroll
            for (int nf = 0; nf < 4; nf++)
                mma_f16(acc[mf][nf], afr[mf], bfr[nf]);
        if (c < 7) { CP_WAIT0; }
        __syncthreads();
    }

    // epilogue: silu + bias, red.v2 scatter into g_agg (fp32)
    #pragma unroll
    for (int mf = 0; mf < 4; mf++) {
        #pragma unroll
        for (int rr = 0; rr < 2; rr++) {
            int m = wm*64 + mf*16 + (lane >> 2) + rr*8;
            float* ap = g_agg + (size_t)s_i[m]*DD;
            #pragma unroll
            for (int nf = 0; nf < 4; nf++) {
                int n = wn*32 + nf*8 + (lane & 3)*2;
                float v0 = silu_f(acc[mf][nf][rr*2 + 0] + eb2[n]);
                float v1 = silu_f(acc[mf][nf][rr*2 + 1] + eb2[n + 1]);
                asm volatile("red.global.add.v2.f32 [%0], {%1, %2};"
                             :: "l"(ap + n), "f"(v0), "f"(v1) : "memory");
            }
        }
    }
}

// ---------------- kernel 5: node MLP, fp16 m16n8k16 ----------------
#define TN 128
#define SAn 264    // bank step 4 -> conflict-free

__global__ __launch_bounds__(256, 2)
void node_kernel(const float* __restrict__ nfeat,
                 const float* __restrict__ nb1, const float* __restrict__ nb2,
                 float* __restrict__ out)
{
    extern __shared__ __half smh[];
    __half* s_a  = smh;               // TN*SAn
    __half* s_bb = smh + TN*SAn;      // 2*BHB
    __shared__ float s_cnt[TN];

    int tid  = threadIdx.x, lane = tid & 31, wid = tid >> 5;
    int wm = wid >> 2, wn = wid & 3;
    int n0 = blockIdx.x * TN;
    int bn = tid >> 1, bs = (tid & 1) * 8;

    if (tid < TN) {
        int n = min(n0 + tid, NN - 1);
        s_cnt[tid] = fmaxf((float)g_cnt[n], 1.f);
    }
    // h rows (fp16 direct)
    #pragma unroll
    for (int it = 0; it < 8; it++) {
        int idx = tid + it*256;
        int r = idx >> 4, seg = idx & 15;
        int n = min(n0 + r, NN - 1);
        cpa16(s_a + r*SAn + seg*8, g_h16 + (size_t)n*DD + seg*8);
    }
    cpa16(s_bb + bn*SBh + bs, g_nw1T + bn*256 + bs);
    CP_COMMIT;
    __syncthreads();   // s_cnt visible

    // agg/cnt -> cols 128..255 (fp32 load, convert)
    #pragma unroll
    for (int it = 0; it < 16; it++) {
        int idx = tid + it*256;
        int r = idx >> 5, c4 = (idx & 31) * 4;
        int n = min(n0 + r, NN - 1);
        float inv = __fdividef(1.f, s_cnt[r]);
        float4 v = *(const float4*)(g_agg + (size_t)n*DD + c4);
        __half* dst = s_a + r*SAn + DD + c4;
        *(__half2*)(dst)     = __floats2half2_rn(v.x * inv, v.y * inv);
        *(__half2*)(dst + 2) = __floats2half2_rn(v.z * inv, v.w * inv);
    }

    float acc[4][4][4];
    #pragma unroll
    for (int mf = 0; mf < 4; mf++)
        #pragma unroll
        for (int nf = 0; nf < 4; nf++)
            #pragma unroll
            for (int u = 0; u < 4; u++) acc[mf][nf][u] = 0.f;

    CP_WAIT0;
    __syncthreads();

    // ---- GEMM1: K=256, 16 chunks ----
    for (int ct = 0; ct < 16; ct++) {
        __half* dbuf = s_bb + ((ct+1)&1)*BHB;
        if (ct < 15) cpa16(dbuf + bn*SBh + bs, g_nw1T + bn*256 + (ct*16 + 16) + bs);
        else         cpa16(dbuf + bn*SBh + bs, g_nw2T + bn*128 + bs);
        CP_COMMIT;
        const __half* bB = s_bb + (ct & 1)*BHB;
        int kg = ct*16;
        uint32_t afr[4][4];
        #pragma unroll
        for (int mf = 0; mf < 4; mf++) LDA16(afr[mf], s_a, SAn, wm*64 + mf*16, kg);
        uint32_t bfr[4][2];
        #pragma unroll
        for (int nf = 0; nf < 4; nf++) LDB16(bfr[nf], bB, SBh, wn*32 + nf*8);
        #pragma unroll
        for (int mf = 0; mf < 4; mf++)
            #pragma unroll
            for (int nf = 0; nf < 4; nf++)
                mma_f16(acc[mf][nf], afr[mf], bfr[nf]);
        CP_WAIT0;
        __syncthreads();
    }

    // hidden -> s_a cols 0..127
    #pragma unroll
    for (int mf = 0; mf < 4; mf++) {
        int r0 = wm*64 + mf*16 + (lane >> 2);
        #pragma unroll
        for (int nf = 0; nf < 4; nf++) {
            int n = wn*32 + nf*8 + (lane & 3)*2;
            float b0 = nb1[n], b1 = nb1[n + 1];
            *(__half2*)(s_a + r0*SAn + n) =
                __floats2half2_rn(silu_f(acc[mf][nf][0] + b0), silu_f(acc[mf][nf][1] + b1));
            *(__half2*)(s_a + (r0 + 8)*SAn + n) =
                __floats2half2_rn(silu_f(acc[mf][nf][2] + b0), silu_f(acc[mf][nf][3] + b1));
            #pragma unroll
            for (int u = 0; u < 4; u++) acc[mf][nf][u] = 0.f;
        }
    }
    __syncthreads();

    // ---- GEMM2: K=128, 8 chunks; chunk c in buf[c&1] ----
    for (int c = 0; c < 8; c++) {
        if (c < 7) {
            cpa16(s_bb + ((c+1)&1)*BHB + bn*SBh + bs, g_nw2T + bn*128 + (c*16 + 16) + bs);
            CP_COMMIT;
        }
        const __half* bB = s_bb + (c & 1)*BHB;
        int kg = c*16;
        uint32_t afr[4][4];
        #pragma unroll
        for (int mf = 0; mf < 4; mf++) LDA16(afr[mf], s_a, SAn, wm*64 + mf*16, kg);
        uint32_t bfr[4][2];
        #pragma unroll
        for (int nf = 0; nf < 4; nf++) LDB16(bfr[nf], bB, SBh, wn*32 + nf*8);
        #pragma unroll
        for (int mf = 0; mf < 4; mf++)
            #pragma unroll
            for (int nf = 0; nf < 4; nf++)
                mma_f16(acc[mf][nf], afr[mf], bfr[nf]);
        if (c < 7) { CP_WAIT0; }
        __syncthreads();
    }

    // epilogue: out = nfeat + silu(acc + nb2)
    #pragma unroll
    for (int mf = 0; mf < 4; mf++) {
        #pragma unroll
        for (int rr = 0; rr < 2; rr++) {
            int m = wm*64 + mf*16 + (lane >> 2) + rr*8;
            int n = n0 + m;
            if (n < NN) {
                const float* nfr = nfeat + (size_t)n*DD;
                float* orow = out + (size_t)n*DD;
                #pragma unroll
                for (int nf = 0; nf < 4; nf++) {
                    int col = wn*32 + nf*8 + (lane & 3)*2;
                    orow[col]     = nfr[col]     + silu_f(acc[mf][nf][rr*2 + 0] + nb2[col]);
                    orow[col + 1] = nfr[col + 1] + silu_f(acc[mf][nf][rr*2 + 1] + nb2[col + 1]);
                }
            }
        }
    }
}

// ---------------- launch ----------------
extern "C" void kernel_launch(void* const* d_in, const int* in_sizes, int n_in,
                              void* d_out, int out_size)
{
    const float* node_features = (const float*)d_in[0];
    const float* cond = (const float*)d_in[1];
    const int*   n2g  = (const int*)d_in[2];
    const float* frac = (const float*)d_in[3];
    const float* lat  = (const float*)d_in[4];
    const int*   edges= (const int*)d_in[5];
    const int*   e2g  = (const int*)d_in[6];
    const float* wq = (const float*)d_in[7];
    const float* bq = (const float*)d_in[8];
    const float* wk = (const float*)d_in[9];
    const float* bk = (const float*)d_in[10];
    const float* wv = (const float*)d_in[11];
    const float* bv = (const float*)d_in[12];
    const float* wo = (const float*)d_in[13];
    const float* bo = (const float*)d_in[14];
    const float* sw1= (const float*)d_in[15];
    const float* sb1= (const float*)d_in[16];
    const float* sw2= (const float*)d_in[17];
    const float* sb2= (const float*)d_in[18];
    const float* ew1= (const float*)d_in[19];
    const float* eb1= (const float*)d_in[20];
    const float* ew2= (const float*)d_in[21];
    const float* eb2= (const float*)d_in[22];
    const float* nw1= (const float*)d_in[23];
    const float* nb1= (const float*)d_in[24];
    const float* nw2= (const float*)d_in[25];
    const float* nb2= (const float*)d_in[26];
    float* out = (float*)d_out;

    const int attn_smem = (2*AT*SAH + 2*BBF + 3072 + 1024 + 128 + 8 + AT*24 + AT*8) * 4;
    const int edge_smem = (TM*SAh + 2*BHB) * 2;   // halfs
    const int node_smem = (TN*SAn + 2*BHB) * 2;
    cudaFuncSetAttribute(attn_kernel, cudaFuncAttributeMaxDynamicSharedMemorySize, attn_smem);
    cudaFuncSetAttribute(edge_kernel, cudaFuncAttributeMaxDynamicSharedMemorySize, edge_smem);
    cudaFuncSetAttribute(node_kernel, cudaFuncAttributeMaxDynamicSharedMemorySize, node_smem);

    prep_kernel<<<BB*TT + BB, 128>>>(cond, wk, bk, wv, bv, lat);
    convw_kernel<<<(DD*272 + 2*DD*DD + DD*256 + 255)/256, 256>>>(ew1, ew2, nw1, nw2);
    zero_kernel<<<(NN*DD + 255) / 256, 256>>>();
    attn_kernel<<<(NN + AT - 1) / AT, 256, attn_smem>>>(node_features, frac, n2g,
                                                        wq, bq, wo, bo, sw1, sb1, sw2, sb2);
    edge_kernel<<<EE / TM, 256, edge_smem>>>(frac, edges, e2g, eb1, eb2);
    node_kernel<<<(NN + TN - 1) / TN, 256, node_smem>>>(node_features, nb1, nb2, out);
}

// round 8
// speedup vs baseline: 2.3117x; 1.0006x over previous
#include <cuda_runtime.h>
#include <cuda_fp16.h>
#include <math.h>
#include <stdint.h>

#define NN 50000
#define EE 800000
#define BB 256
#define DD 128
#define TT 8
#define KV_OFF (BB*TT*DD)

// ---------------- scratch (no allocations allowed) ----------------
__device__ __half g_h16[(size_t)NN*DD];     // post-attention node states (fp16)
__device__ float  g_KV[2*BB*TT*DD];         // Kc then Vc (fp32)
__device__ float  g_lip[BB*9];              // lattice inner products
__device__ float  g_agg[(size_t)NN*DD];     // scatter sums (fp32 atomics)
__device__ int    g_cnt[NN];                // scatter counts
// pre-converted, pre-transposed fp16 weights [N][K]
__device__ __half g_ew1T[DD*272];
__device__ __half g_ew2T[DD*DD];
__device__ __half g_nw1T[DD*256];
__device__ __half g_nw2T[DD*DD];

__device__ __forceinline__ float silu_f(float x) {
    return __fdividef(x, 1.f + __expf(-x));
}

// tf32 mma (attention kernel only)
__device__ __forceinline__ void mma_tf32(float* c, const uint32_t* a, const uint32_t* b) {
    asm volatile(
        "mma.sync.aligned.m16n8k8.row.col.f32.tf32.tf32.f32 "
        "{%0,%1,%2,%3}, {%4,%5,%6,%7}, {%8,%9}, {%0,%1,%2,%3};\n"
        : "+f"(c[0]), "+f"(c[1]), "+f"(c[2]), "+f"(c[3])
        : "r"(a[0]), "r"(a[1]), "r"(a[2]), "r"(a[3]), "r"(b[0]), "r"(b[1]));
}
// fp16 mma, fp32 accumulate
__device__ __forceinline__ void mma_f16(float* c, const uint32_t* a, const uint32_t* b) {
    asm volatile(
        "mma.sync.aligned.m16n8k16.row.col.f32.f16.f16.f32 "
        "{%0,%1,%2,%3}, {%4,%5,%6,%7}, {%8,%9}, {%0,%1,%2,%3};\n"
        : "+f"(c[0]), "+f"(c[1]), "+f"(c[2]), "+f"(c[3])
        : "r"(a[0]), "r"(a[1]), "r"(a[2]), "r"(a[3]), "r"(b[0]), "r"(b[1]));
}

__device__ __forceinline__ void cpa16(void* dst, const void* src) {
    uint32_t d = (uint32_t)__cvta_generic_to_shared(dst);
    asm volatile("cp.async.cg.shared.global [%0], [%1], 16;" :: "r"(d), "l"(src));
}
#define CP_COMMIT asm volatile("cp.async.commit_group;" ::: "memory")
#define CP_WAIT0  asm volatile("cp.async.wait_group 0;" ::: "memory")

// -------- fp16 fragment loads (A row-major [m][k], B as [n][k]) --------
#define LDA16(afr, base, SAx, rowbase, kg)                                        \
    {                                                                             \
        const __half* ap_ = (base) + ((rowbase) + (lane >> 2))*(SAx) + (kg) + ((lane & 3)*2); \
        afr[0] = *(const uint32_t*)(ap_);                                         \
        afr[1] = *(const uint32_t*)(ap_ + 8*(SAx));                               \
        afr[2] = *(const uint32_t*)(ap_ + 8);                                     \
        afr[3] = *(const uint32_t*)(ap_ + 8*(SAx) + 8);                           \
    }
#define LDB16(bfr, bB, SBx, ncol)                                                 \
    {                                                                             \
        const __half* bp_ = (bB) + ((ncol) + (lane >> 2))*(SBx) + ((lane & 3)*2); \
        bfr[0] = *(const uint32_t*)(bp_);                                         \
        bfr[1] = *(const uint32_t*)(bp_ + 8);                                     \
    }

// tf32 frag loads (attn)
#define SB 136
#define BBF (16*SB)
#define LOAD_AFRAG(afr, s_a, SAx, rowbase, kg)                                   \
    {                                                                            \
        const float* ap_ = (s_a) + ((rowbase) + (lane >> 2))*(SAx) + (kg) + (lane & 3); \
        afr[0] = __float_as_uint(ap_[0]);                                        \
        afr[1] = __float_as_uint(ap_[8*(SAx)]);                                  \
        afr[2] = __float_as_uint(ap_[4]);                                        \
        afr[3] = __float_as_uint(ap_[8*(SAx) + 4]);                              \
    }
#define LOAD_BFRAG(bfr, bB, kk, ncol)                                            \
    {                                                                            \
        const float* bp_ = (bB) + ((kk) + (lane & 3))*SB + (ncol) + (lane >> 2); \
        bfr[0] = __float_as_uint(bp_[0]);                                        \
        bfr[1] = __float_as_uint(bp_[4*SB]);                                     \
    }

// ---------------- kernel 1: K/V projection + lattice gram ----------------
__global__ void prep_kernel(const float* __restrict__ cond,
                            const float* __restrict__ wk, const float* __restrict__ bk,
                            const float* __restrict__ wv, const float* __restrict__ bv,
                            const float* __restrict__ lat)
{
    int b = blockIdx.x;
    if (b < BB*TT) {
        __shared__ float s_c[DD];
        int d = threadIdx.x;
        s_c[d] = cond[b*DD + d];
        __syncthreads();
        float ka = bk[d], va = bv[d];
        #pragma unroll 8
        for (int k = 0; k < DD; k++) {
            float c = s_c[k];
            ka = fmaf(c, wk[k*DD + d], ka);
            va = fmaf(c, wv[k*DD + d], va);
        }
        g_KV[b*DD + d] = ka;
        g_KV[KV_OFF + b*DD + d] = va;
    } else {
        int bb = b - BB*TT;
        int t = threadIdx.x;
        if (t < 9) {
            int i = t / 3, k2 = t % 3;
            const float* L = lat + bb*9;
            g_lip[bb*9 + t] = L[i*3+0]*L[k2*3+0] + L[i*3+1]*L[k2*3+1] + L[i*3+2]*L[k2*3+2];
        }
    }
}

// ---------------- kernel 1b: convert+transpose weights to fp16 [N][K] ----------------
__global__ void convw_kernel(const float* __restrict__ ew1, const float* __restrict__ ew2,
                             const float* __restrict__ nw1, const float* __restrict__ nw2)
{
    int idx = blockIdx.x * 256 + threadIdx.x;
    if (idx < DD*272) {
        int n = idx / 272, k = idx % 272;
        g_ew1T[idx] = (k < 268) ? __float2half(ew1[k*DD + n]) : __half(0.f);
    } else if (idx < DD*272 + DD*DD) {
        int j = idx - DD*272;
        int n = j / DD, k = j % DD;
        g_ew2T[j] = __float2half(ew2[k*DD + n]);
    } else if (idx < DD*272 + DD*DD + DD*256) {
        int j = idx - DD*272 - DD*DD;
        int n = j / 256, k = j % 256;
        g_nw1T[j] = __float2half(nw1[k*DD + n]);
    } else if (idx < DD*272 + 2*DD*DD + DD*256) {
        int j = idx - DD*272 - DD*DD - DD*256;
        int n = j / DD, k = j % DD;
        g_nw2T[j] = __float2half(nw2[k*DD + n]);
    }
}

// ---------------- kernel 2: zero scatter buffers ----------------
__global__ void zero_kernel()
{
    int idx = blockIdx.x * blockDim.x + threadIdx.x;
    if (idx < NN*DD) g_agg[idx] = 0.f;
    if (idx < NN)    g_cnt[idx] = 0;
}

// ---------------- kernel 3: cross-attention (tf32 mma), writes g_h16 ----------------
#define AT 64
#define SAH 132

__global__ __launch_bounds__(256, 2)
void attn_kernel(const float* __restrict__ nfeat, const float* __restrict__ frac,
                 const int* __restrict__ n2g,
                 const float* __restrict__ wq, const float* __restrict__ bq,
                 const float* __restrict__ wo, const float* __restrict__ bo,
                 const float* __restrict__ sw1, const float* __restrict__ sb1,
                 const float* __restrict__ sw2, const float* __restrict__ sb2)
{
    extern __shared__ float sm[];
    float* s_h   = sm;
    float* s_q   = s_h + AT*SAH;
    float* s_bb  = s_q + AT*SAH;
    float* s_sw1 = s_bb + 2*BBF;
    float* s_sw2 = s_sw1 + 3072;
    float* s_sb1 = s_sw2 + 1024;
    float* s_sb2 = s_sb1 + 128;
    float* s_enc = s_sb2 + 8;
    float* s_att = s_enc + AT*24;
    __shared__ int s_g[AT];

    int tid = threadIdx.x, lane = tid & 31, wid = tid >> 5;
    int wm = wid >> 2, wn = wid & 3;
    int n0 = blockIdx.x * AT;
    int brow = tid >> 5, bc4 = (tid & 31) * 4;

    if (tid < AT) s_g[tid] = n2g[min(n0 + tid, NN - 1)];

    #pragma unroll
    for (int it = 0; it < 8; it++) {
        int idx = tid + it*256;
        int r = idx >> 5, c4 = (idx & 31) * 4;
        int n = min(n0 + r, NN - 1);
        cpa16(s_h + r*SAH + c4, nfeat + (size_t)n*DD + c4);
    }
    #pragma unroll
    for (int it = 0; it < 3; it++) {
        int idx = tid + it*256;
        cpa16(s_sw1 + idx*4, sw1 + idx*4);
    }
    cpa16(s_sw2 + tid*4, sw2 + tid*4);
    if (tid < 32) cpa16(s_sb1 + tid*4, sb1 + tid*4);
    if (tid < 2)  cpa16(s_sb2 + tid*4, sb2 + tid*4);
    cpa16(s_bb + brow*SB + bc4, wq + (size_t)brow*DD + bc4);
    cpa16(s_bb + (brow+8)*SB + bc4, wq + (size_t)(brow+8)*DD + bc4);
    CP_COMMIT;

    {
        int n = tid >> 2, sub = tid & 3;
        int nn = min(n0 + n, NN - 1);
        float f0 = frac[nn*3+0], f1 = frac[nn*3+1], f2 = frac[nn*3+2];
        #pragma unroll
        for (int k = sub; k < 24; k += 4) {
            int ii = k % 12, c = ii >> 2, j = ii & 3;
            float fv = (c == 0) ? f0 : ((c == 1) ? f1 : f2);
            float ph = fv * ((float)(1 << j) * 3.14159265358979323846f);
            s_enc[n*24 + k] = (k < 12) ? sinf(ph) : cosf(ph);
        }
    }
    CP_WAIT0;
    __syncthreads();

    float acc[2][4][4];
    #pragma unroll
    for (int mf = 0; mf < 2; mf++)
        #pragma unroll
        for (int nf = 0; nf < 4; nf++)
            #pragma unroll
            for (int u = 0; u < 4; u++) acc[mf][nf][u] = 0.f;

    for (int ct = 0; ct < 8; ct++) {
        const float* wsrc = (ct < 7) ? (wq + (size_t)(ct*16 + 16)*DD) : wo;
        float* dbuf = s_bb + ((ct+1)&1)*BBF;
        cpa16(dbuf + brow*SB + bc4, wsrc + (size_t)brow*DD + bc4);
        cpa16(dbuf + (brow+8)*SB + bc4, wsrc + (size_t)(brow+8)*DD + bc4);
        CP_COMMIT;
        const float* bB = s_bb + (ct & 1)*BBF;
        #pragma unroll
        for (int kk = 0; kk < 16; kk += 8) {
            int kg = ct*16 + kk;
            uint32_t afr[2][4];
            #pragma unroll
            for (int mf = 0; mf < 2; mf++) LOAD_AFRAG(afr[mf], s_h, SAH, wm*32 + mf*16, kg);
            uint32_t bfr[4][2];
            #pragma unroll
            for (int nf = 0; nf < 4; nf++) LOAD_BFRAG(bfr[nf], bB, kk, wn*32 + nf*8);
            #pragma unroll
            for (int mf = 0; mf < 2; mf++)
                #pragma unroll
                for (int nf = 0; nf < 4; nf++)
                    mma_tf32(acc[mf][nf], afr[mf], bfr[nf]);
        }
        CP_WAIT0;
        __syncthreads();
    }
    #pragma unroll
    for (int mf = 0; mf < 2; mf++) {
        int r0 = wm*32 + mf*16 + (lane >> 2);
        #pragma unroll
        for (int nf = 0; nf < 4; nf++) {
            int n = wn*32 + nf*8 + (lane & 3)*2;
            float b0 = bq[n], b1 = bq[n + 1];
            s_q[r0*SAH + n]           = acc[mf][nf][0] + b0;
            s_q[r0*SAH + n + 1]       = acc[mf][nf][1] + b1;
            s_q[(r0 + 8)*SAH + n]     = acc[mf][nf][2] + b0;
            s_q[(r0 + 8)*SAH + n + 1] = acc[mf][nf][3] + b1;
            #pragma unroll
            for (int u = 0; u < 4; u++) acc[mf][nf][u] = 0.f;
        }
    }
    __syncthreads();

    {
        int n = tid >> 2, sub = tid & 3;
        int gg = s_g[n];
        float b8[8];
        #pragma unroll
        for (int t = 0; t < 8; t++) b8[t] = 0.f;
        const float* en = s_enc + n*24;
        for (int cc = 0; cc < 32; cc++) {
            int c = cc*4 + sub;
            float hid = s_sb1[c];
            #pragma unroll
            for (int k = 0; k < 24; k++) hid = fmaf(en[k], s_sw1[k*DD + c], hid);
            hid = silu_f(hid);
            #pragma unroll
            for (int t = 0; t < 8; t++) b8[t] = fmaf(hid, s_sw2[c*8 + t], b8[t]);
        }
        #pragma unroll
        for (int t = 0; t < 8; t++) {
            b8[t] += __shfl_xor_sync(0xffffffffu, b8[t], 1, 4);
            b8[t] += __shfl_xor_sync(0xffffffffu, b8[t], 2, 4);
        }
        int t0 = sub*2, t1 = t0 + 1;
        const float* K0 = g_KV + (size_t)(gg*TT + t0)*DD;
        const float* K1 = K0 + DD;
        const float* qq = s_q + n*SAH;
        float sc0 = 0.f, sc1 = 0.f;
        #pragma unroll 8
        for (int k = 0; k < DD; k++) {
            float qv = qq[k];
            sc0 = fmaf(qv, K0[k], sc0);
            sc1 = fmaf(qv, K1[k], sc1);
        }
        float v0 = sc0 * 0.08838834764831845f + b8[t0] + s_sb2[t0];
        float v1 = sc1 * 0.08838834764831845f + b8[t1] + s_sb2[t1];
        float m = fmaxf(v0, v1);
        m = fmaxf(m, __shfl_xor_sync(0xffffffffu, m, 1, 4));
        m = fmaxf(m, __shfl_xor_sync(0xffffffffu, m, 2, 4));
        float e0 = __expf(v0 - m), e1 = __expf(v1 - m);
        float s = e0 + e1;
        s += __shfl_xor_sync(0xffffffffu, s, 1, 4);
        s += __shfl_xor_sync(0xffffffffu, s, 2, 4);
        float inv = __fdividef(1.f, s);
        s_att[n*8 + t0] = e0 * inv;
        s_att[n*8 + t1] = e1 * inv;
    }
    __syncthreads();

    #pragma unroll
    for (int it = 0; it < 32; it++) {
        int idx = tid + it*256;
        int n = idx >> 7, c = idx & 127;
        const float* Vr = g_KV + KV_OFF + (size_t)s_g[n]*TT*DD + c;
        const float* at = s_att + n*8;
        float a = 0.f;
        #pragma unroll
        for (int t = 0; t < 8; t++) a = fmaf(at[t], Vr[t*DD], a);
        s_q[n*SAH + c] = a;
    }
    __syncthreads();

    for (int c = 0; c < 8; c++) {
        if (c < 7) {
            float* dbuf = s_bb + ((c+1)&1)*BBF;
            cpa16(dbuf + brow*SB + bc4, wo + (size_t)(c*16 + 16 + brow)*DD + bc4);
            cpa16(dbuf + (brow+8)*SB + bc4, wo + (size_t)(c*16 + 24 + brow)*DD + bc4);
            CP_COMMIT;
        }
        const float* bB = s_bb + (c & 1)*BBF;
        #pragma unroll
        for (int kk = 0; kk < 16; kk += 8) {
            int kg = c*16 + kk;
            uint32_t afr[2][4];
            #pragma unroll
            for (int mf = 0; mf < 2; mf++) LOAD_AFRAG(afr[mf], s_q, SAH, wm*32 + mf*16, kg);
            uint32_t bfr[4][2];
            #pragma unroll
            for (int nf = 0; nf < 4; nf++) LOAD_BFRAG(bfr[nf], bB, kk, wn*32 + nf*8);
            #pragma unroll
            for (int mf = 0; mf < 2; mf++)
                #pragma unroll
                for (int nf = 0; nf < 4; nf++)
                    mma_tf32(acc[mf][nf], afr[mf], bfr[nf]);
        }
        if (c < 7) { CP_WAIT0; }
        __syncthreads();
    }

    // epilogue: g_h16 = half(h + ca@wo + bo)
    #pragma unroll
    for (int mf = 0; mf < 2; mf++) {
        #pragma unroll
        for (int rr = 0; rr < 2; rr++) {
            int m = wm*32 + mf*16 + (lane >> 2) + rr*8;
            int n = n0 + m;
            if (n < NN) {
                __half* orow = g_h16 + (size_t)n*DD;
                const float* hrow = s_h + m*SAH;
                #pragma unroll
                for (int nf = 0; nf < 4; nf++) {
                    int col = wn*32 + nf*8 + (lane & 3)*2;
                    float v0 = hrow[col]     + acc[mf][nf][rr*2 + 0] + bo[col];
                    float v1 = hrow[col + 1] + acc[mf][nf][rr*2 + 1] + bo[col + 1];
                    *(__half2*)(orow + col) = __floats2half2_rn(v0, v1);
                }
            }
        }
    }
}

// ---------------- kernel 4: edge MLP, fp16 m16n8k16 ----------------
// Tile 128 edges x 128 outs, 8 warps (2 wm x 4 wn), warp tile 64x32 (mf=4, nf=4).
#define TM 128
#define SAh 280    // A stride halfs; bank step 12 -> conflict-free
#define SBh 24     // B stride halfs (16 k + 8 pad); bank step 12 -> conflict-free
#define BHB (128*SBh)

__global__ __launch_bounds__(256, 2)
void edge_kernel(const float* __restrict__ frac,
                 const int* __restrict__ edges, const int* __restrict__ e2g,
                 const float* __restrict__ eb1, const float* __restrict__ eb2)
{
    extern __shared__ __half smh[];
    __half* s_a  = smh;               // TM*SAh halfs
    __half* s_bb = smh + TM*SAh;      // 2*BHB halfs
    __shared__ int s_i[TM], s_j[TM];

    int tid  = threadIdx.x, lane = tid & 31, wid = tid >> 5;
    int wm = wid >> 2, wn = wid & 3;
    int e0 = blockIdx.x * TM;
    int bn = tid >> 1, bs = (tid & 1) * 8;   // B coop-load: row n, seg

    if (tid < TM) {
        s_i[tid] = edges[e0 + tid];
        s_j[tid] = edges[EE + e0 + tid];
    }
    if (tid >= 128 && tid < 256) {
        // nothing
    }
    __syncthreads();

    // async gather A rows (fp16, 16B = 8 halfs per seg; 128 edges x 2 rows x 16 segs)
    #pragma unroll
    for (int it = 0; it < 16; it++) {
        int idx = tid + it*256;
        int r = idx >> 4, seg = idx & 15;
        int e = r >> 1, p = r & 1;
        int node = p ? s_j[e] : s_i[e];
        cpa16(s_a + e*SAh + p*DD + seg*8, g_h16 + (size_t)node*DD + seg*8);
    }
    // ew1T chunk 0 -> buf0
    cpa16(s_bb + bn*SBh + bs, g_ew1T + bn*272 + bs);
    CP_COMMIT;

    // tail cols 256..279 (lip, fd, pad) + counts
    if (tid < TM) {
        int e = tid;
        const float* lp = g_lip + e2g[e0 + e]*9;
        #pragma unroll
        for (int u = 0; u < 9; u++) s_a[e*SAh + 256 + u] = __float2half(lp[u]);
        int ii = s_i[e], jj = s_j[e];
        #pragma unroll
        for (int c = 0; c < 3; c++) {
            float dd = frac[jj*3 + c] - frac[ii*3 + c];
            dd -= floorf(dd);
            s_a[e*SAh + 265 + c] = __float2half(dd);
        }
        #pragma unroll
        for (int u = 268; u < 280; u++) s_a[e*SAh + u] = __half(0.f);
        atomicAdd(&g_cnt[ii], 1);
    }

    float acc[4][4][4];
    #pragma unroll
    for (int mf = 0; mf < 4; mf++)
        #pragma unroll
        for (int nf = 0; nf < 4; nf++)
            #pragma unroll
            for (int u = 0; u < 4; u++) acc[mf][nf][u] = 0.f;

    CP_WAIT0;
    __syncthreads();

    // ---- GEMM1: K=272, 17 chunks of K=16 ----
    for (int ct = 0; ct < 17; ct++) {
        __half* dbuf = s_bb + ((ct+1)&1)*BHB;
        if (ct < 16) cpa16(dbuf + bn*SBh + bs, g_ew1T + bn*272 + (ct*16 + 16) + bs);
        else         cpa16(dbuf + bn*SBh + bs, g_ew2T + bn*128 + bs);
        CP_COMMIT;
        const __half* bB = s_bb + (ct & 1)*BHB;
        int kg = ct*16;
        uint32_t afr[4][4];
        #pragma unroll
        for (int mf = 0; mf < 4; mf++) LDA16(afr[mf], s_a, SAh, wm*64 + mf*16, kg);
        uint32_t bfr[4][2];
        #pragma unroll
        for (int nf = 0; nf < 4; nf++) LDB16(bfr[nf], bB, SBh, wn*32 + nf*8);
        #pragma unroll
        for (int mf = 0; mf < 4; mf++)
            #pragma unroll
            for (int nf = 0; nf < 4; nf++)
                mma_f16(acc[mf][nf], afr[mf], bfr[nf]);
        CP_WAIT0;
        __syncthreads();
    }

    // hidden = silu(acc + eb1) -> s_a cols 0..127 (half2 stores)
    #pragma unroll
    for (int mf = 0; mf < 4; mf++) {
        int r0 = wm*64 + mf*16 + (lane >> 2);
        #pragma unroll
        for (int nf = 0; nf < 4; nf++) {
            int n = wn*32 + nf*8 + (lane & 3)*2;
            float b0 = eb1[n], b1 = eb1[n + 1];
            *(__half2*)(s_a + r0*SAh + n) =
                __floats2half2_rn(silu_f(acc[mf][nf][0] + b0), silu_f(acc[mf][nf][1] + b1));
            *(__half2*)(s_a + (r0 + 8)*SAh + n) =
                __floats2half2_rn(silu_f(acc[mf][nf][2] + b0), silu_f(acc[mf][nf][3] + b1));
            #pragma unroll
            for (int u = 0; u < 4; u++) acc[mf][nf][u] = 0.f;
        }
    }
    __syncthreads();

    // ---- GEMM2: K=128, 8 chunks; chunk c in buf[(1+c)&1] ----
    for (int c = 0; c < 8; c++) {
        if (c < 7) {
            cpa16(s_bb + (c & 1)*BHB + bn*SBh + bs, g_ew2T + bn*128 + (c*16 + 16) + bs);
            CP_COMMIT;
        }
        const __half* bB = s_bb + ((1 + c) & 1)*BHB;
        int kg = c*16;
        uint32_t afr[4][4];
        #pragma unroll
        for (int mf = 0; mf < 4; mf++) LDA16(afr[mf], s_a, SAh, wm*64 + mf*16, kg);
        uint32_t bfr[4][2];
        #pragma unroll
        for (int nf = 0; nf < 4; nf++) LDB16(bfr[nf], bB, SBh, wn*32 + nf*8);
        #pragma unroll
        for (int mf = 0; mf < 4; mf++)
            #pragma unroll
            for (int nf = 0; nf < 4; nf++)
                mma_f16(acc[mf][nf], afr[mf], bfr[nf]);
        if (c < 7) { CP_WAIT0; }
        __syncthreads();
    }

    // epilogue: silu + bias, red.v2 scatter into g_agg (fp32)
    #pragma unroll
    for (int mf = 0; mf < 4; mf++) {
        #pragma unroll
        for (int rr = 0; rr < 2; rr++) {
            int m = wm*64 + mf*16 + (lane >> 2) + rr*8;
            float* ap = g_agg + (size_t)s_i[m]*DD;
            #pragma unroll
            for (int nf = 0; nf < 4; nf++) {
                int n = wn*32 + nf*8 + (lane & 3)*2;
                float v0 = silu_f(acc[mf][nf][rr*2 + 0] + eb2[n]);
                float v1 = silu_f(acc[mf][nf][rr*2 + 1] + eb2[n + 1]);
                asm volatile("red.global.add.v2.f32 [%0], {%1, %2};"
                             :: "l"(ap + n), "f"(v0), "f"(v1) : "memory");
            }
        }
    }
}

// ---------------- kernel 5: node MLP, fp16 m16n8k16 ----------------
#define TN 128
#define SAn 264    // bank step 4 -> conflict-free

__global__ __launch_bounds__(256, 2)
void node_kernel(const float* __restrict__ nfeat,
                 const float* __restrict__ nb1, const float* __restrict__ nb2,
                 float* __restrict__ out)
{
    extern __shared__ __half smh[];
    __half* s_a  = smh;               // TN*SAn
    __half* s_bb = smh + TN*SAn;      // 2*BHB
    __shared__ float s_cnt[TN];

    int tid  = threadIdx.x, lane = tid & 31, wid = tid >> 5;
    int wm = wid >> 2, wn = wid & 3;
    int n0 = blockIdx.x * TN;
    int bn = tid >> 1, bs = (tid & 1) * 8;

    if (tid < TN) {
        int n = min(n0 + tid, NN - 1);
        s_cnt[tid] = fmaxf((float)g_cnt[n], 1.f);
    }
    // h rows (fp16 direct)
    #pragma unroll
    for (int it = 0; it < 8; it++) {
        int idx = tid + it*256;
        int r = idx >> 4, seg = idx & 15;
        int n = min(n0 + r, NN - 1);
        cpa16(s_a + r*SAn + seg*8, g_h16 + (size_t)n*DD + seg*8);
    }
    cpa16(s_bb + bn*SBh + bs, g_nw1T + bn*256 + bs);
    CP_COMMIT;
    __syncthreads();   // s_cnt visible

    // agg/cnt -> cols 128..255 (fp32 load, convert)
    #pragma unroll
    for (int it = 0; it < 16; it++) {
        int idx = tid + it*256;
        int r = idx >> 5, c4 = (idx & 31) * 4;
        int n = min(n0 + r, NN - 1);
        float inv = __fdividef(1.f, s_cnt[r]);
        float4 v = *(const float4*)(g_agg + (size_t)n*DD + c4);
        __half* dst = s_a + r*SAn + DD + c4;
        *(__half2*)(dst)     = __floats2half2_rn(v.x * inv, v.y * inv);
        *(__half2*)(dst + 2) = __floats2half2_rn(v.z * inv, v.w * inv);
    }

    float acc[4][4][4];
    #pragma unroll
    for (int mf = 0; mf < 4; mf++)
        #pragma unroll
        for (int nf = 0; nf < 4; nf++)
            #pragma unroll
            for (int u = 0; u < 4; u++) acc[mf][nf][u] = 0.f;

    CP_WAIT0;
    __syncthreads();

    // ---- GEMM1: K=256, 16 chunks ----
    for (int ct = 0; ct < 16; ct++) {
        __half* dbuf = s_bb + ((ct+1)&1)*BHB;
        if (ct < 15) cpa16(dbuf + bn*SBh + bs, g_nw1T + bn*256 + (ct*16 + 16) + bs);
        else         cpa16(dbuf + bn*SBh + bs, g_nw2T + bn*128 + bs);
        CP_COMMIT;
        const __half* bB = s_bb + (ct & 1)*BHB;
        int kg = ct*16;
        uint32_t afr[4][4];
        #pragma unroll
        for (int mf = 0; mf < 4; mf++) LDA16(afr[mf], s_a, SAn, wm*64 + mf*16, kg);
        uint32_t bfr[4][2];
        #pragma unroll
        for (int nf = 0; nf < 4; nf++) LDB16(bfr[nf], bB, SBh, wn*32 + nf*8);
        #pragma unroll
        for (int mf = 0; mf < 4; mf++)
            #pragma unroll
            for (int nf = 0; nf < 4; nf++)
                mma_f16(acc[mf][nf], afr[mf], bfr[nf]);
        CP_WAIT0;
        __syncthreads();
    }

    // hidden -> s_a cols 0..127
    #pragma unroll
    for (int mf = 0; mf < 4; mf++) {
        int r0 = wm*64 + mf*16 + (lane >> 2);
        #pragma unroll
        for (int nf = 0; nf < 4; nf++) {
            int n = wn*32 + nf*8 + (lane & 3)*2;
            float b0 = nb1[n], b1 = nb1[n + 1];
            *(__half2*)(s_a + r0*SAn + n) =
                __floats2half2_rn(silu_f(acc[mf][nf][0] + b0), silu_f(acc[mf][nf][1] + b1));
            *(__half2*)(s_a + (r0 + 8)*SAn + n) =
                __floats2half2_rn(silu_f(acc[mf][nf][2] + b0), silu_f(acc[mf][nf][3] + b1));
            #pragma unroll
            for (int u = 0; u < 4; u++) acc[mf][nf][u] = 0.f;
        }
    }
    __syncthreads();

    // ---- GEMM2: K=128, 8 chunks; chunk c in buf[c&1] ----
    for (int c = 0; c < 8; c++) {
        if (c < 7) {
            cpa16(s_bb + ((c+1)&1)*BHB + bn*SBh + bs, g_nw2T + bn*128 + (c*16 + 16) + bs);
            CP_COMMIT;
        }
        const __half* bB = s_bb + (c & 1)*BHB;
        int kg = c*16;
        uint32_t afr[4][4];
        #pragma unroll
        for (int mf = 0; mf < 4; mf++) LDA16(afr[mf], s_a, SAn, wm*64 + mf*16, kg);
        uint32_t bfr[4][2];
        #pragma unroll
        for (int nf = 0; nf < 4; nf++) LDB16(bfr[nf], bB, SBh, wn*32 + nf*8);
        #pragma unroll
        for (int mf = 0; mf < 4; mf++)
            #pragma unroll
            for (int nf = 0; nf < 4; nf++)
                mma_f16(acc[mf][nf], afr[mf], bfr[nf]);
        if (c < 7) { CP_WAIT0; }
        __syncthreads();
    }

    // epilogue: out = nfeat + silu(acc + nb2)
    #pragma unroll
    for (int mf = 0; mf < 4; mf++) {
        #pragma unroll
        for (int rr = 0; rr < 2; rr++) {
            int m = wm*64 + mf*16 + (lane >> 2) + rr*8;
            int n = n0 + m;
            if (n < NN) {
                const float* nfr = nfeat + (size_t)n*DD;
                float* orow = out + (size_t)n*DD;
                #pragma unroll
                for (int nf = 0; nf < 4; nf++) {
                    int col = wn*32 + nf*8 + (lane & 3)*2;
                    orow[col]     = nfr[col]     + silu_f(acc[mf][nf][rr*2 + 0] + nb2[col]);
                    orow[col + 1] = nfr[col + 1] + silu_f(acc[mf][nf][rr*2 + 1] + nb2[col + 1]);
                }
            }
        }
    }
}

// ---------------- launch ----------------
extern "C" void kernel_launch(void* const* d_in, const int* in_sizes, int n_in,
                              void* d_out, int out_size)
{
    const float* node_features = (const float*)d_in[0];
    const float* cond = (const float*)d_in[1];
    const int*   n2g  = (const int*)d_in[2];
    const float* frac = (const float*)d_in[3];
    const float* lat  = (const float*)d_in[4];
    const int*   edges= (const int*)d_in[5];
    const int*   e2g  = (const int*)d_in[6];
    const float* wq = (const float*)d_in[7];
    const float* bq = (const float*)d_in[8];
    const float* wk = (const float*)d_in[9];
    const float* bk = (const float*)d_in[10];
    const float* wv = (const float*)d_in[11];
    const float* bv = (const float*)d_in[12];
    const float* wo = (const float*)d_in[13];
    const float* bo = (const float*)d_in[14];
    const float* sw1= (const float*)d_in[15];
    const float* sb1= (const float*)d_in[16];
    const float* sw2= (const float*)d_in[17];
    const float* sb2= (const float*)d_in[18];
    const float* ew1= (const float*)d_in[19];
    const float* eb1= (const float*)d_in[20];
    const float* ew2= (const float*)d_in[21];
    const float* eb2= (const float*)d_in[22];
    const float* nw1= (const float*)d_in[23];
    const float* nb1= (const float*)d_in[24];
    const float* nw2= (const float*)d_in[25];
    const float* nb2= (const float*)d_in[26];
    float* out = (float*)d_out;

    const int attn_smem = (2*AT*SAH + 2*BBF + 3072 + 1024 + 128 + 8 + AT*24 + AT*8) * 4;
    const int edge_smem = (TM*SAh + 2*BHB) * 2;   // halfs
    const int node_smem = (TN*SAn + 2*BHB) * 2;
    cudaFuncSetAttribute(attn_kernel, cudaFuncAttributeMaxDynamicSharedMemorySize, attn_smem);
    cudaFuncSetAttribute(edge_kernel, cudaFuncAttributeMaxDynamicSharedMemorySize, edge_smem);
    cudaFuncSetAttribute(node_kernel, cudaFuncAttributeMaxDynamicSharedMemorySize, node_smem);

    prep_kernel<<<BB*TT + BB, 128>>>(cond, wk, bk, wv, bv, lat);
    convw_kernel<<<(DD*272 + 2*DD*DD + DD*256 + 255)/256, 256>>>(ew1, ew2, nw1, nw2);
    zero_kernel<<<(NN*DD + 255) / 256, 256>>>();
    attn_kernel<<<(NN + AT - 1) / AT, 256, attn_smem>>>(node_features, frac, n2g,
                                                        wq, bq, wo, bo, sw1, sb1, sw2, sb2);
    edge_kernel<<<EE / TM, 256, edge_smem>>>(frac, edges, e2g, eb1, eb2);
    node_kernel<<<(NN + TN - 1) / TN, 256, node_smem>>>(node_features, nb1, nb2, out);
}